// round 4
// baseline (speedup 1.0000x reference)
#include <cuda_runtime.h>
#include <cstdint>

#define B_ 8
#define N_ 8192
#define Q_ 1024
#define S_ 32
#define M_ (B_*Q_*S_)          // 262144
#define R2_ 0.04f
#define ALPHA_ 0.2f
#define EPS_ 1e-5f

// ---------------- scratch (device globals: no allocations allowed) ----------------
__device__ float g_x0[(size_t)67*M_];          // [67][M]  grouped input
__device__ float g_y0[(size_t)64*M_];          // layer0 raw output
__device__ float g_y1[(size_t)128*M_];         // layer1 raw output
__device__ float g_ft[(size_t)B_*N_*64];       // features transposed [B][N][64]
__device__ float g_gmax[(size_t)256*B_*Q_];    // layer2 max over S (pre-BN)
__device__ int   g_nidx[M_];                   // ball query indices
__device__ float g_st0[2*64], g_st1[2*128], g_st2[2*256];   // [sum | sumsq]
__device__ float g_ac0[2*64], g_ac1[2*128], g_ac2[2*256];   // [a | c] per channel

__device__ __forceinline__ float lrelu(float v){ return v >= 0.f ? v : ALPHA_*v; }

__device__ __forceinline__ void ffma2(unsigned long long &d, unsigned long long a, unsigned long long b){
    asm("fma.rn.f32x2 %0, %1, %2, %0;" : "+l"(d) : "l"(a), "l"(b));
}
__device__ __forceinline__ float2 u2f2(unsigned long long u){
    float2 f; asm("mov.b64 {%0,%1}, %2;" : "=f"(f.x), "=f"(f.y) : "l"(u)); return f;
}

// ---------------- FPS: one block per batch, 1024 threads, 8 pts/thread ----------------
__global__ void __launch_bounds__(1024) fps_kernel(const float* __restrict__ xyz,
                                                   float* __restrict__ newxyz){
    int b = blockIdx.x, t = threadIdx.x;
    const float* px = xyz + (size_t)b*N_*3;
    float X[8], Y[8], Z[8], D[8];
#pragma unroll
    for (int i=0;i<8;i++){
        int p = t*8+i;
        X[i]=px[p*3+0]; Y[i]=px[p*3+1]; Z[i]=px[p*3+2]; D[i]=1e10f;
    }
    __shared__ float s_last[3];
    __shared__ float s_val[32];
    __shared__ int   s_idx[32];
    if (t==0){
        s_last[0]=px[0]; s_last[1]=px[1]; s_last[2]=px[2];
        newxyz[0 + (size_t)b*Q_*3]=px[0];
        newxyz[1 + (size_t)b*Q_*3]=px[1];
        newxyz[2 + (size_t)b*Q_*3]=px[2];
    }
    __syncthreads();
    for (int j=1;j<Q_;j++){
        float lx=s_last[0], ly=s_last[1], lz=s_last[2];
        float best=-1.f; int bi=0;
#pragma unroll
        for (int i=0;i<8;i++){
            float dx=X[i]-lx, dy=Y[i]-ly, dz=Z[i]-lz;
            float d = dx*dx + dy*dy + dz*dz;
            float nd = fminf(D[i], d); D[i]=nd;
            if (nd > best){ best=nd; bi=t*8+i; }   // strict > keeps lowest index on ties
        }
#pragma unroll
        for (int o=16;o>0;o>>=1){
            float ov = __shfl_down_sync(0xffffffffu, best, o);
            int   oi = __shfl_down_sync(0xffffffffu, bi,   o);
            if (ov > best || (ov == best && oi < bi)){ best=ov; bi=oi; }
        }
        if ((t&31)==0){ s_val[t>>5]=best; s_idx[t>>5]=bi; }
        __syncthreads();
        if (t < 32){
            best = s_val[t]; bi = s_idx[t];
#pragma unroll
            for (int o=16;o>0;o>>=1){
                float ov = __shfl_down_sync(0xffffffffu, best, o);
                int   oi = __shfl_down_sync(0xffffffffu, bi,   o);
                if (ov > best || (ov == best && oi < bi)){ best=ov; bi=oi; }
            }
            if (t==0){
                const float* pp = px + (size_t)bi*3;
                float ax=pp[0], ay=pp[1], az=pp[2];
                s_last[0]=ax; s_last[1]=ay; s_last[2]=az;
                float* o = newxyz + (size_t)(b*Q_+j)*3;
                o[0]=ax; o[1]=ay; o[2]=az;
            }
        }
        __syncthreads();
    }
}

// ---------------- Ball query: one warp per (b,q) ----------------
// d2 rounding bit-matches XLA: squares individually rounded then left-assoc
// summed (no fma contraction); dot = ascending cuBLAS-style fma chain;
// d2 = RN( RN(qsq+xsq) - 2*dot )  (2*dot exact).
__global__ void __launch_bounds__(256) ballquery_kernel(const float* __restrict__ xyz,
                                                        const float* __restrict__ newxyz,
                                                        int* __restrict__ nidx){
    int w = (blockIdx.x*256 + threadIdx.x) >> 5;   // 0..8191
    int lane = threadIdx.x & 31;
    int b = w >> 10;
    const float* px = xyz + (size_t)b*N_*3;
    const float* pq = newxyz + (size_t)w*3;
    float qx=pq[0], qy=pq[1], qz=pq[2];
    float qsq = __fadd_rn(__fadd_rn(__fmul_rn(qx,qx), __fmul_rn(qy,qy)), __fmul_rn(qz,qz));
    int* out = nidx + (size_t)w*S_;
    int cnt = 0, first = 0;
    for (int base=0; base<N_ && cnt<S_; base+=32){
        int p = base + lane;
        float x=px[p*3+0], y=px[p*3+1], z=px[p*3+2];
        float xsq = __fadd_rn(__fadd_rn(__fmul_rn(x,x), __fmul_rn(y,y)), __fmul_rn(z,z));
        float dot = __fmaf_rn(qz, z, __fmaf_rn(qy, y, __fmul_rn(qx, x)));
        float d2  = __fadd_rn(__fadd_rn(qsq, xsq), __fmul_rn(-2.0f, dot));
        bool in = d2 < R2_;
        unsigned bal = __ballot_sync(0xffffffffu, in);
        if (bal){
            if (cnt == 0) first = base + __ffs(bal) - 1;
            int r = __popc(bal & ((1u << lane) - 1u));
            if (in && (cnt + r < S_)) out[cnt + r] = p;
            cnt += __popc(bal);
        }
    }
    if (cnt < S_){
        int pad = (cnt > 0) ? first : 0;
        if (lane >= cnt) out[lane] = pad;
    }
}

// ---------------- features [B][64][N] -> ft [B][N][64] ----------------
__global__ void __launch_bounds__(256) transpose_feat(const float* __restrict__ f,
                                                      float* __restrict__ ft){
    __shared__ float st[64][33];
    int b = blockIdx.y;
    int n0 = blockIdx.x*32;
    int tid = threadIdx.x;
    int nn = tid & 31, c0 = tid >> 5;
#pragma unroll
    for (int c = c0; c < 64; c += 8)
        st[c][nn] = f[((size_t)b*64 + c)*N_ + n0 + nn];
    __syncthreads();
#pragma unroll
    for (int e = tid; e < 2048; e += 256){
        int nl = e >> 6, c = e & 63;
        ft[((size_t)b*N_ + n0 + nl)*64 + c] = st[c][nl];
    }
}

// ---------------- build x0 [67][M]: rel xyz + gathered features ----------------
__global__ void __launch_bounds__(256) build_x0(const float* __restrict__ xyz,
                                                const float* __restrict__ nxyz,
                                                const float* __restrict__ ft,
                                                const int* __restrict__ nidx,
                                                float* __restrict__ x0){
    int m = blockIdx.x*256 + threadIdx.x;
    int b = m >> 15;
    int q = (m >> 5) & (Q_-1);
    int p = nidx[m];
    const float* pc = xyz + ((size_t)b*N_ + p)*3;
    const float* qc = nxyz + ((size_t)(b*Q_ + q))*3;
    x0[(size_t)0*M_ + m] = pc[0]-qc[0];
    x0[(size_t)1*M_ + m] = pc[1]-qc[1];
    x0[(size_t)2*M_ + m] = pc[2]-qc[2];
    const float4* fr = (const float4*)(ft + ((size_t)b*N_ + p)*64);
#pragma unroll
    for (int c4=0;c4<16;c4++){
        float4 v = fr[c4];
        x0[(size_t)(3+4*c4+0)*M_ + m] = v.x;
        x0[(size_t)(3+4*c4+1)*M_ + m] = v.y;
        x0[(size_t)(3+4*c4+2)*M_ + m] = v.z;
        x0[(size_t)(3+4*c4+3)*M_ + m] = v.w;
    }
}

__global__ void zero_stats(){
    int t = threadIdx.x;
    if (t < 128) g_st0[t]=0.f;
    if (t < 256) g_st1[t]=0.f;
    g_st2[t]=0.f;   // t < 512
}

// ---------------- GEMM: Y[COUT][M] = W X (+bias), f32x2 packed FFMA, exact fp32 ----------------
// TRANS: apply leaky(a*v+c) (prev layer's BN+LeakyReLU) while loading X.
// DOMAX: skip global Y store; block-local max over S -> gmax (M tile = 4 full S groups).
template<int CIN, int COUT, bool TRANS, bool DOMAX>
__global__ void __launch_bounds__(256,2) gemm_kernel(
    const float* __restrict__ W, const float* __restrict__ bias,
    const float* __restrict__ Xin, const float* __restrict__ ac,
    float* __restrict__ Yout, float* __restrict__ gstats, float* __restrict__ gmax)
{
    constexpr int KC=32, MT=128, CT=64;
    __shared__ __align__(16) float smem[KC*CT*2 + KC*MT];   // 32 KB: Wt(splat f32x2) | Xt
    __shared__ float sstat[2*CT];
    float2* Wt = (float2*)smem;                 // [KC][CT] splatted
    float*  Xt = smem + KC*CT*2;                // [KC][MT]
    int tid = threadIdx.x;
    int tx = tid & 15, ty = tid >> 4;
    int mbase = blockIdx.x * MT;
    int cbase = blockIdx.y * CT;
    if (tid < 2*CT) sstat[tid] = 0.f;

    unsigned long long acc[4][4] = {};
    constexpr int NCH = (CIN + KC - 1)/KC;
    for (int ch=0; ch<NCH; ++ch){
        int k0 = ch*KC;
        __syncthreads();
#pragma unroll
        for (int e = tid; e < KC*CT; e += 256){
            int kk = e >> 6, c = e & 63;
            int k = k0 + kk;
            float w = (k < CIN) ? W[(size_t)(cbase+c)*CIN + k] : 0.f;
            Wt[kk*CT + c] = make_float2(w, w);
        }
#pragma unroll
        for (int e = tid; e < KC*MT/4; e += 256){
            int kk = e >> 5, m4 = e & 31;
            int k = k0 + kk;
            float4 v = make_float4(0.f,0.f,0.f,0.f);
            if (k < CIN){
                v = *(const float4*)(Xin + (size_t)k*M_ + mbase + m4*4);
                if constexpr (TRANS){
                    float a = ac[k], c2 = ac[CIN + k];
                    v.x = lrelu(a*v.x + c2);
                    v.y = lrelu(a*v.y + c2);
                    v.z = lrelu(a*v.z + c2);
                    v.w = lrelu(a*v.w + c2);
                }
            }
            *(float4*)(Xt + kk*MT + m4*4) = v;
        }
        __syncthreads();
#pragma unroll
        for (int kk=0; kk<KC; ++kk){
            ulonglong2 wa = *(const ulonglong2*)(Wt + kk*CT + ty*4);
            ulonglong2 wb = *(const ulonglong2*)(Wt + kk*CT + ty*4 + 2);
            ulonglong2 xa = *(const ulonglong2*)(Xt + kk*MT + tx*8);
            ulonglong2 xb = *(const ulonglong2*)(Xt + kk*MT + tx*8 + 4);
            unsigned long long wv[4] = {wa.x, wa.y, wb.x, wb.y};
            unsigned long long xv[4] = {xa.x, xa.y, xb.x, xb.y};
#pragma unroll
            for (int i=0;i<4;i++)
#pragma unroll
                for (int jj=0;jj<4;jj++)
                    ffma2(acc[i][jj], wv[i], xv[jj]);
        }
    }
    __syncthreads();

    float vals[4][8];
#pragma unroll
    for (int i=0;i<4;i++){
        float bi = bias[cbase + ty*4 + i];
        float s1 = 0.f, s2 = 0.f;
#pragma unroll
        for (int jj=0;jj<4;jj++){
            float2 f = u2f2(acc[i][jj]);
            f.x += bi; f.y += bi;
            vals[i][2*jj]   = f.x;
            vals[i][2*jj+1] = f.y;
            s1 += f.x + f.y;
            s2 += f.x*f.x + f.y*f.y;
        }
        atomicAdd(&sstat[ty*4 + i], s1);
        atomicAdd(&sstat[CT + ty*4 + i], s2);
    }
    if constexpr (DOMAX){
#pragma unroll
        for (int i=0;i<4;i++){
            *(float4*)(smem + (ty*4+i)*MT + tx*8)     = make_float4(vals[i][0],vals[i][1],vals[i][2],vals[i][3]);
            *(float4*)(smem + (ty*4+i)*MT + tx*8 + 4) = make_float4(vals[i][4],vals[i][5],vals[i][6],vals[i][7]);
        }
    } else {
#pragma unroll
        for (int i=0;i<4;i++){
            float* yp = Yout + (size_t)(cbase + ty*4 + i)*M_ + mbase + tx*8;
            *(float4*)yp     = make_float4(vals[i][0],vals[i][1],vals[i][2],vals[i][3]);
            *(float4*)(yp+4) = make_float4(vals[i][4],vals[i][5],vals[i][6],vals[i][7]);
        }
    }
    __syncthreads();
    if (tid < CT)            atomicAdd(&gstats[cbase + tid], sstat[tid]);
    else if (tid < 2*CT)     atomicAdd(&gstats[COUT + cbase + (tid - CT)], sstat[tid]);
    if constexpr (DOMAX){
        int c = tid >> 2, qi = tid & 3;
        const float* row = smem + c*MT + qi*32;
        float mx = row[0];
#pragma unroll
        for (int s=1;s<32;s++) mx = fmaxf(mx, row[s]);
        gmax[(size_t)(cbase + c)*(B_*Q_) + (mbase >> 5) + qi] = mx;
    }
}

template<int COUT>
__global__ void compute_ac(const float* __restrict__ st, const float* __restrict__ g,
                           const float* __restrict__ beta, float* __restrict__ ac){
    int c = threadIdx.x;
    if (c >= COUT) return;
    float inv  = 1.f/(float)M_;
    float mean = st[c]*inv;
    float var  = st[COUT+c]*inv - mean*mean;
    float a    = g[c]*rsqrtf(var + EPS_);
    ac[c]      = a;
    ac[COUT+c] = beta[c] - a*mean;
}

// out[b][c][q] = leaky(a2[c]*max + c2[c])   (BN+LeakyReLU commute with max since a2>0)
__global__ void __launch_bounds__(256) final_kernel(const float* __restrict__ gmax,
                                                    const float* __restrict__ ac,
                                                    float* __restrict__ out){
    int i = blockIdx.x*256 + threadIdx.x;
    int q = i & (Q_-1);
    int c = (i >> 10) & 255;
    int b = i >> 18;
    float a = ac[c], c2 = ac[256+c];
    out[i] = lrelu(a*gmax[(size_t)c*(B_*Q_) + b*Q_ + q] + c2);
}

extern "C" void kernel_launch(void* const* d_in, const int* in_sizes, int n_in,
                              void* d_out, int out_size) {
    const float* xyz  = (const float*)d_in[0];
    const float* feat = (const float*)d_in[1];
    const float* W0 = (const float*)d_in[2];
    const float* b0 = (const float*)d_in[3];
    const float* gg0= (const float*)d_in[4];
    const float* be0= (const float*)d_in[5];
    const float* W1 = (const float*)d_in[6];
    const float* b1 = (const float*)d_in[7];
    const float* gg1= (const float*)d_in[8];
    const float* be1= (const float*)d_in[9];
    const float* W2 = (const float*)d_in[10];
    const float* b2 = (const float*)d_in[11];
    const float* gg2= (const float*)d_in[12];
    const float* be2= (const float*)d_in[13];

    float* out = (float*)d_out;
    float* newxyz  = out;                          // [B][Q][3]
    float* outfeat = out + (size_t)B_*Q_*3;        // [B][256][Q]

    float *x0p,*y0p,*y1p,*ftp,*gmaxp,*st0p,*st1p,*st2p,*ac0p,*ac1p,*ac2p; int* idxp;
    cudaGetSymbolAddress((void**)&x0p,  g_x0);
    cudaGetSymbolAddress((void**)&y0p,  g_y0);
    cudaGetSymbolAddress((void**)&y1p,  g_y1);
    cudaGetSymbolAddress((void**)&ftp,  g_ft);
    cudaGetSymbolAddress((void**)&gmaxp,g_gmax);
    cudaGetSymbolAddress((void**)&idxp, g_nidx);
    cudaGetSymbolAddress((void**)&st0p, g_st0);
    cudaGetSymbolAddress((void**)&st1p, g_st1);
    cudaGetSymbolAddress((void**)&st2p, g_st2);
    cudaGetSymbolAddress((void**)&ac0p, g_ac0);
    cudaGetSymbolAddress((void**)&ac1p, g_ac1);
    cudaGetSymbolAddress((void**)&ac2p, g_ac2);

    fps_kernel<<<B_, 1024>>>(xyz, newxyz);
    ballquery_kernel<<<(B_*Q_)/8, 256>>>(xyz, newxyz, idxp);
    transpose_feat<<<dim3(N_/32, B_), 256>>>(feat, ftp);
    build_x0<<<M_/256, 256>>>(xyz, newxyz, ftp, idxp, x0p);
    zero_stats<<<1, 512>>>();

    gemm_kernel<67,64,false,false><<<dim3(M_/128, 1), 256>>>(W0, b0, x0p, nullptr, y0p, st0p, nullptr);
    compute_ac<64><<<1, 64>>>(st0p, gg0, be0, ac0p);

    gemm_kernel<64,128,true,false><<<dim3(M_/128, 2), 256>>>(W1, b1, y0p, ac0p, y1p, st1p, nullptr);
    compute_ac<128><<<1, 128>>>(st1p, gg1, be1, ac1p);

    gemm_kernel<128,256,true,true><<<dim3(M_/128, 4), 256>>>(W2, b2, y1p, ac1p, nullptr, st2p, gmaxp);
    compute_ac<256><<<1, 256>>>(st2p, gg2, be2, ac2p);

    final_kernel<<<(B_*256*Q_)/256, 256>>>(gmaxp, ac2p, outfeat);
}

// round 5
// speedup vs baseline: 1.4900x; 1.4900x over previous
#include <cuda_runtime.h>
#include <cstdint>

#define B_ 8
#define N_ 8192
#define Q_ 1024
#define S_ 32
#define M_ (B_*Q_*S_)          // 262144
#define R2_ 0.04f
#define ALPHA_ 0.2f
#define EPS_ 1e-5f

// ---------------- scratch (device globals: no allocations allowed) ----------------
__device__ float g_x0[(size_t)67*M_];          // [67][M]  grouped input
__device__ float g_y0[(size_t)64*M_];          // layer0 raw output
__device__ float g_y1[(size_t)128*M_];         // layer1 raw output
__device__ float g_ft[(size_t)B_*N_*64];       // features transposed [B][N][64]
__device__ float g_gmax[(size_t)256*B_*Q_];    // layer2 max over S (pre-BN)
__device__ int   g_nidx[M_];                   // ball query indices
__device__ float g_st0[2*64], g_st1[2*128], g_st2[2*256];   // [sum | sumsq]
__device__ float g_ac0[2*64], g_ac1[2*128], g_ac2[2*256];   // [a | c] per channel
__device__ float g_wt0[96*64];                 // W0^T padded to K=96
__device__ float g_wt1[64*128];                // W1^T
__device__ float g_wt2[128*256];               // W2^T

__device__ __forceinline__ float lrelu(float v){ return v >= 0.f ? v : ALPHA_*v; }

typedef unsigned long long u64;
__device__ __forceinline__ void ffma2(u64 &d, u64 a, u64 b){
    asm("fma.rn.f32x2 %0, %1, %2, %0;" : "+l"(d) : "l"(a), "l"(b));
}
__device__ __forceinline__ u64 fma2n(u64 a, u64 b, u64 c){
    u64 d; asm("fma.rn.f32x2 %0, %1, %2, %3;" : "=l"(d) : "l"(a), "l"(b), "l"(c)); return d;
}
__device__ __forceinline__ u64 add2(u64 a, u64 b){
    u64 d; asm("add.rn.f32x2 %0, %1, %2;" : "=l"(d) : "l"(a), "l"(b)); return d;
}
__device__ __forceinline__ u64 mul2(u64 a, u64 b){
    u64 d; asm("mul.rn.f32x2 %0, %1, %2;" : "=l"(d) : "l"(a), "l"(b)); return d;
}
__device__ __forceinline__ u64 pack2(float lo, float hi){
    u64 d; asm("mov.b64 %0, {%1,%2};" : "=l"(d) : "f"(lo), "f"(hi)); return d;
}
__device__ __forceinline__ u64 splat2(float v){
    u64 d; asm("mov.b64 %0, {%1,%1};" : "=l"(d) : "f"(v)); return d;
}
__device__ __forceinline__ float2 u2f2(u64 u){
    float2 f; asm("mov.b64 {%0,%1}, %2;" : "=f"(f.x), "=f"(f.y) : "l"(u)); return f;
}

// ---------------- FPS: one block per batch, 1024 threads, 8 pts/thread (f32x2) ----------------
__global__ void __launch_bounds__(1024) fps_kernel(const float* __restrict__ xyz,
                                                   float* __restrict__ newxyz){
    int b = blockIdx.x, t = threadIdx.x;
    const float* px = xyz + (size_t)b*N_*3;
    u64 X2[4], Y2[4], Z2[4];
    float D[8];
#pragma unroll
    for (int i=0;i<4;i++){
        int p0 = t*8 + 2*i, p1 = p0 + 1;
        X2[i] = pack2(px[p0*3+0], px[p1*3+0]);
        Y2[i] = pack2(px[p0*3+1], px[p1*3+1]);
        Z2[i] = pack2(px[p0*3+2], px[p1*3+2]);
        D[2*i] = 1e10f; D[2*i+1] = 1e10f;
    }
    __shared__ float s_last[3];
    __shared__ float s_val[32];
    __shared__ int   s_idx[32];
    if (t==0){
        s_last[0]=px[0]; s_last[1]=px[1]; s_last[2]=px[2];
        newxyz[0 + (size_t)b*Q_*3]=px[0];
        newxyz[1 + (size_t)b*Q_*3]=px[1];
        newxyz[2 + (size_t)b*Q_*3]=px[2];
    }
    __syncthreads();
    for (int j=1;j<Q_;j++){
        u64 nlx = splat2(-s_last[0]);
        u64 nly = splat2(-s_last[1]);
        u64 nlz = splat2(-s_last[2]);
        float best=-1.f; int bi=0;
#pragma unroll
        for (int i=0;i<4;i++){
            u64 dx = add2(X2[i], nlx);          // RN(x - lx) per lane
            u64 dy = add2(Y2[i], nly);
            u64 dz = add2(Z2[i], nlz);
            u64 tt = mul2(dx, dx);
            tt = fma2n(dy, dy, tt);
            tt = fma2n(dz, dz, tt);
            float2 d = u2f2(tt);
            float n0 = fminf(D[2*i],   d.x); D[2*i]   = n0;
            float n1 = fminf(D[2*i+1], d.y); D[2*i+1] = n1;
            if (n0 > best){ best=n0; bi=t*8+2*i; }      // strict > keeps lowest index
            if (n1 > best){ best=n1; bi=t*8+2*i+1; }
        }
#pragma unroll
        for (int o=16;o>0;o>>=1){
            float ov = __shfl_down_sync(0xffffffffu, best, o);
            int   oi = __shfl_down_sync(0xffffffffu, bi,   o);
            if (ov > best || (ov == best && oi < bi)){ best=ov; bi=oi; }
        }
        if ((t&31)==0){ s_val[t>>5]=best; s_idx[t>>5]=bi; }
        __syncthreads();
        if (t < 32){
            best = s_val[t]; bi = s_idx[t];
#pragma unroll
            for (int o=16;o>0;o>>=1){
                float ov = __shfl_down_sync(0xffffffffu, best, o);
                int   oi = __shfl_down_sync(0xffffffffu, bi,   o);
                if (ov > best || (ov == best && oi < bi)){ best=ov; bi=oi; }
            }
            if (t==0){
                const float* pp = px + (size_t)bi*3;
                float ax=pp[0], ay=pp[1], az=pp[2];
                s_last[0]=ax; s_last[1]=ay; s_last[2]=az;
                float* o = newxyz + (size_t)(b*Q_+j)*3;
                o[0]=ax; o[1]=ay; o[2]=az;
            }
        }
        __syncthreads();
    }
}

// ---------------- Ball query: one warp per (b,q) ----------------
__global__ void __launch_bounds__(256) ballquery_kernel(const float* __restrict__ xyz,
                                                        const float* __restrict__ newxyz,
                                                        int* __restrict__ nidx){
    int w = (blockIdx.x*256 + threadIdx.x) >> 5;   // 0..8191
    int lane = threadIdx.x & 31;
    int b = w >> 10;
    const float* px = xyz + (size_t)b*N_*3;
    const float* pq = newxyz + (size_t)w*3;
    float qx=pq[0], qy=pq[1], qz=pq[2];
    float qsq = __fadd_rn(__fadd_rn(__fmul_rn(qx,qx), __fmul_rn(qy,qy)), __fmul_rn(qz,qz));
    int* out = nidx + (size_t)w*S_;
    int cnt = 0, first = 0;
    for (int base=0; base<N_ && cnt<S_; base+=32){
        int p = base + lane;
        float x=px[p*3+0], y=px[p*3+1], z=px[p*3+2];
        float xsq = __fadd_rn(__fadd_rn(__fmul_rn(x,x), __fmul_rn(y,y)), __fmul_rn(z,z));
        float dot = __fmaf_rn(qz, z, __fmaf_rn(qy, y, __fmul_rn(qx, x)));
        float d2  = __fadd_rn(__fadd_rn(qsq, xsq), __fmul_rn(-2.0f, dot));
        bool in = d2 < R2_;
        unsigned bal = __ballot_sync(0xffffffffu, in);
        if (bal){
            if (cnt == 0) first = base + __ffs(bal) - 1;
            int r = __popc(bal & ((1u << lane) - 1u));
            if (in && (cnt + r < S_)) out[cnt + r] = p;
            cnt += __popc(bal);
        }
    }
    if (cnt < S_){
        int pad = (cnt > 0) ? first : 0;
        if (lane >= cnt) out[lane] = pad;
    }
}

// ---------------- features [B][64][N] -> ft [B][N][64] ----------------
__global__ void __launch_bounds__(256) transpose_feat(const float* __restrict__ f,
                                                      float* __restrict__ ft){
    __shared__ float st[64][33];
    int b = blockIdx.y;
    int n0 = blockIdx.x*32;
    int tid = threadIdx.x;
    int nn = tid & 31, c0 = tid >> 5;
#pragma unroll
    for (int c = c0; c < 64; c += 8)
        st[c][nn] = f[((size_t)b*64 + c)*N_ + n0 + nn];
    __syncthreads();
#pragma unroll
    for (int e = tid; e < 2048; e += 256){
        int nl = e >> 6, c = e & 63;
        ft[((size_t)b*N_ + n0 + nl)*64 + c] = st[c][nl];
    }
}

// ---------------- build x0 [67][M]: rel xyz + gathered features ----------------
__global__ void __launch_bounds__(256) build_x0(const float* __restrict__ xyz,
                                                const float* __restrict__ nxyz,
                                                const float* __restrict__ ft,
                                                const int* __restrict__ nidx,
                                                float* __restrict__ x0){
    int m = blockIdx.x*256 + threadIdx.x;
    int b = m >> 15;
    int q = (m >> 5) & (Q_-1);
    int p = nidx[m];
    const float* pc = xyz + ((size_t)b*N_ + p)*3;
    const float* qc = nxyz + ((size_t)(b*Q_ + q))*3;
    x0[(size_t)0*M_ + m] = pc[0]-qc[0];
    x0[(size_t)1*M_ + m] = pc[1]-qc[1];
    x0[(size_t)2*M_ + m] = pc[2]-qc[2];
    const float4* fr = (const float4*)(ft + ((size_t)b*N_ + p)*64);
#pragma unroll
    for (int c4=0;c4<16;c4++){
        float4 v = fr[c4];
        x0[(size_t)(3+4*c4+0)*M_ + m] = v.x;
        x0[(size_t)(3+4*c4+1)*M_ + m] = v.y;
        x0[(size_t)(3+4*c4+2)*M_ + m] = v.z;
        x0[(size_t)(3+4*c4+3)*M_ + m] = v.w;
    }
}

__global__ void zero_stats(){
    int t = threadIdx.x;
    if (t < 128) g_st0[t]=0.f;
    if (t < 256) g_st1[t]=0.f;
    g_st2[t]=0.f;   // t < 512
}

// ---------------- W[c][k] -> WT[k][c], zero-padded in k ----------------
__global__ void transpose_w(const float* __restrict__ W, float* __restrict__ WT,
                            int CIN, int COUT, int KPAD){
    int idx = blockIdx.x*256 + threadIdx.x;
    if (idx >= KPAD*COUT) return;
    int k = idx / COUT, c = idx - k*COUT;
    WT[idx] = (k < CIN) ? W[c*CIN + k] : 0.f;
}

// ---------------- GEMM: Y[COUT][M] = W X (+bias), f32x2, 8m x CPT-cout per thread ----
// WT: [KPAD][COUT] (pre-transposed, zero-padded). Same per-element accumulation
// order as R4 (kk-sequential, f32x2 over adjacent m) -> bit-identical outputs.
// TRANS: apply leaky(a*v+c) while loading X. DOMAX: shuffle max over S -> gmax.
template<int CIN, int KPAD, int COUT, int CT, bool TRANS, bool DOMAX>
__global__ void __launch_bounds__(256,2) gemm_kernel(
    const float* __restrict__ WT, const float* __restrict__ bias,
    const float* __restrict__ Xin, const float* __restrict__ ac,
    float* __restrict__ Yout, float* __restrict__ gstats, float* __restrict__ gmax)
{
    constexpr int KC=32, MT=128;
    constexpr int CPT = CT/16;                  // couts per thread (4 or 8)
    __shared__ __align__(16) float sW[KC*CT];
    __shared__ __align__(16) float sX[KC*MT];
    int tid = threadIdx.x;
    int tx = tid & 15, ty = tid >> 4;
    int mbase = blockIdx.x * MT;
    int cbase = blockIdx.y * CT;

    u64 acc[CPT][4] = {};
    constexpr int NCH = KPAD/KC;
#pragma unroll 1
    for (int ch=0; ch<NCH; ++ch){
        int k0 = ch*KC;
        __syncthreads();
#pragma unroll
        for (int e = tid; e < KC*CT/4; e += 256){
            int kk = e / (CT/4), c4 = e - kk*(CT/4);
            *(float4*)&sW[kk*CT + c4*4] =
                *(const float4*)&WT[(size_t)(k0+kk)*COUT + cbase + c4*4];
        }
#pragma unroll
        for (int e = tid; e < KC*MT/4; e += 256){
            int kk = e >> 5, m4 = e & 31;
            int k = k0 + kk;
            float4 v = make_float4(0.f,0.f,0.f,0.f);
            if (k < CIN){
                v = *(const float4*)(Xin + (size_t)k*M_ + mbase + m4*4);
                if constexpr (TRANS){
                    float a = ac[k], c2 = ac[CIN + k];
                    v.x = lrelu(a*v.x + c2);
                    v.y = lrelu(a*v.y + c2);
                    v.z = lrelu(a*v.z + c2);
                    v.w = lrelu(a*v.w + c2);
                }
            }
            *(float4*)&sX[kk*MT + m4*4] = v;
        }
        __syncthreads();
#pragma unroll
        for (int kk=0; kk<KC; ++kk){
            float warr[CPT];
#pragma unroll
            for (int i4=0; i4<CPT/4; i4++){
                float4 w4 = *(const float4*)&sW[kk*CT + ty*CPT + i4*4];
                warr[i4*4+0]=w4.x; warr[i4*4+1]=w4.y; warr[i4*4+2]=w4.z; warr[i4*4+3]=w4.w;
            }
            u64 wsp[CPT];
#pragma unroll
            for (int i=0;i<CPT;i++) wsp[i] = splat2(warr[i]);
            ulonglong2 xa = *(const ulonglong2*)&sX[kk*MT + tx*8];
            ulonglong2 xb = *(const ulonglong2*)&sX[kk*MT + tx*8 + 4];
            u64 xv[4] = {xa.x, xa.y, xb.x, xb.y};
#pragma unroll
            for (int i=0;i<CPT;i++)
#pragma unroll
                for (int jj=0;jj<4;jj++)
                    ffma2(acc[i][jj], wsp[i], xv[jj]);
        }
    }

    // -------- epilogue: one cout row at a time (keeps registers bounded) --------
#pragma unroll
    for (int i=0;i<CPT;i++){
        int c = cbase + ty*CPT + i;
        float bi = bias[c];
        float vals[8];
        float s1 = 0.f, s2 = 0.f;
#pragma unroll
        for (int jj=0;jj<4;jj++){
            float2 f = u2f2(acc[i][jj]);
            f.x += bi; f.y += bi;
            vals[2*jj] = f.x; vals[2*jj+1] = f.y;
            s1 += f.x + f.y;
            s2 += f.x*f.x + f.y*f.y;
        }
        // stats: reduce across the 16 tx lanes (shfl xor stays within half-warp)
#pragma unroll
        for (int o=1;o<16;o<<=1){
            s1 += __shfl_xor_sync(0xffffffffu, s1, o);
            s2 += __shfl_xor_sync(0xffffffffu, s2, o);
        }
        if (tx==0){
            atomicAdd(&gstats[c], s1);
            atomicAdd(&gstats[COUT + c], s2);
        }
        if constexpr (DOMAX){
            float v = vals[0];
#pragma unroll
            for (int s=1;s<8;s++) v = fmaxf(v, vals[s]);
            v = fmaxf(v, __shfl_xor_sync(0xffffffffu, v, 1));
            v = fmaxf(v, __shfl_xor_sync(0xffffffffu, v, 2));
            if ((tx&3)==0)
                gmax[(size_t)c*(B_*Q_) + (mbase>>5) + (tx>>2)] = v;
        } else {
            float* yp = Yout + (size_t)c*M_ + mbase + tx*8;
            *(float4*)yp     = make_float4(vals[0],vals[1],vals[2],vals[3]);
            *(float4*)(yp+4) = make_float4(vals[4],vals[5],vals[6],vals[7]);
        }
    }
}

template<int COUT>
__global__ void compute_ac(const float* __restrict__ st, const float* __restrict__ g,
                           const float* __restrict__ beta, float* __restrict__ ac){
    int c = threadIdx.x;
    if (c >= COUT) return;
    float inv  = 1.f/(float)M_;
    float mean = st[c]*inv;
    float var  = st[COUT+c]*inv - mean*mean;
    float a    = g[c]*rsqrtf(var + EPS_);
    ac[c]      = a;
    ac[COUT+c] = beta[c] - a*mean;
}

// out[b][c][q] = leaky(a2[c]*max + c2[c])   (BN+LeakyReLU commute with max since a2>0)
__global__ void __launch_bounds__(256) final_kernel(const float* __restrict__ gmax,
                                                    const float* __restrict__ ac,
                                                    float* __restrict__ out){
    int i = blockIdx.x*256 + threadIdx.x;
    int q = i & (Q_-1);
    int c = (i >> 10) & 255;
    int b = i >> 18;
    float a = ac[c], c2 = ac[256+c];
    out[i] = lrelu(a*gmax[(size_t)c*(B_*Q_) + b*Q_ + q] + c2);
}

extern "C" void kernel_launch(void* const* d_in, const int* in_sizes, int n_in,
                              void* d_out, int out_size) {
    const float* xyz  = (const float*)d_in[0];
    const float* feat = (const float*)d_in[1];
    const float* W0 = (const float*)d_in[2];
    const float* b0 = (const float*)d_in[3];
    const float* gg0= (const float*)d_in[4];
    const float* be0= (const float*)d_in[5];
    const float* W1 = (const float*)d_in[6];
    const float* b1 = (const float*)d_in[7];
    const float* gg1= (const float*)d_in[8];
    const float* be1= (const float*)d_in[9];
    const float* W2 = (const float*)d_in[10];
    const float* b2 = (const float*)d_in[11];
    const float* gg2= (const float*)d_in[12];
    const float* be2= (const float*)d_in[13];

    float* out = (float*)d_out;
    float* newxyz  = out;                          // [B][Q][3]
    float* outfeat = out + (size_t)B_*Q_*3;        // [B][256][Q]

    float *x0p,*y0p,*y1p,*ftp,*gmaxp,*st0p,*st1p,*st2p,*ac0p,*ac1p,*ac2p;
    float *wt0p,*wt1p,*wt2p; int* idxp;
    cudaGetSymbolAddress((void**)&x0p,  g_x0);
    cudaGetSymbolAddress((void**)&y0p,  g_y0);
    cudaGetSymbolAddress((void**)&y1p,  g_y1);
    cudaGetSymbolAddress((void**)&ftp,  g_ft);
    cudaGetSymbolAddress((void**)&gmaxp,g_gmax);
    cudaGetSymbolAddress((void**)&idxp, g_nidx);
    cudaGetSymbolAddress((void**)&st0p, g_st0);
    cudaGetSymbolAddress((void**)&st1p, g_st1);
    cudaGetSymbolAddress((void**)&st2p, g_st2);
    cudaGetSymbolAddress((void**)&ac0p, g_ac0);
    cudaGetSymbolAddress((void**)&ac1p, g_ac1);
    cudaGetSymbolAddress((void**)&ac2p, g_ac2);
    cudaGetSymbolAddress((void**)&wt0p, g_wt0);
    cudaGetSymbolAddress((void**)&wt1p, g_wt1);
    cudaGetSymbolAddress((void**)&wt2p, g_wt2);

    fps_kernel<<<B_, 1024>>>(xyz, newxyz);
    ballquery_kernel<<<(B_*Q_)/8, 256>>>(xyz, newxyz, idxp);
    transpose_feat<<<dim3(N_/32, B_), 256>>>(feat, ftp);
    build_x0<<<M_/256, 256>>>(xyz, newxyz, ftp, idxp, x0p);
    zero_stats<<<1, 512>>>();
    transpose_w<<<(96*64+255)/256,   256>>>(W0, wt0p, 67, 64, 96);
    transpose_w<<<(64*128+255)/256,  256>>>(W1, wt1p, 64, 128, 64);
    transpose_w<<<(128*256+255)/256, 256>>>(W2, wt2p, 128, 256, 128);

    gemm_kernel<67,96,64,64,false,false><<<dim3(M_/128, 1), 256>>>(wt0p, b0, x0p, nullptr, y0p, st0p, nullptr);
    compute_ac<64><<<1, 64>>>(st0p, gg0, be0, ac0p);

    gemm_kernel<64,64,128,128,true,false><<<dim3(M_/128, 1), 256>>>(wt1p, b1, y0p, ac0p, y1p, st1p, nullptr);
    compute_ac<128><<<1, 128>>>(st1p, gg1, be1, ac1p);

    gemm_kernel<128,128,256,128,true,true><<<dim3(M_/128, 2), 256>>>(wt2p, b2, y1p, ac1p, nullptr, st2p, gmaxp);
    compute_ac<256><<<1, 256>>>(st2p, gg2, be2, ac2p);

    final_kernel<<<(B_*256*Q_)/256, 256>>>(gmaxp, ac2p, outfeat);
}

// round 6
// speedup vs baseline: 1.8533x; 1.2439x over previous
#include <cuda_runtime.h>
#include <cstdint>

#define B_ 8
#define N_ 8192
#define Q_ 1024
#define S_ 32
#define M_ (B_*Q_*S_)          // 262144
#define R2_ 0.04f
#define ALPHA_ 0.2f
#define EPS_ 1e-5f

// ---------------- scratch (device globals: no allocations allowed) ----------------
__device__ float g_x0[(size_t)67*M_];          // [67][M]  grouped input
__device__ float g_y0[(size_t)64*M_];          // layer0 raw output
__device__ float g_y1[(size_t)128*M_];         // layer1 raw output
__device__ float g_ft[(size_t)B_*N_*64];       // features transposed [B][N][64]
__device__ float g_gmax[(size_t)256*B_*Q_];    // layer2 max over S (pre-BN)
__device__ int   g_nidx[M_];                   // ball query indices
__device__ float g_st0[2*64], g_st1[2*128], g_st2[2*256];   // [sum | sumsq]
__device__ float g_ac0[2*64], g_ac1[2*128], g_ac2[2*256];   // [a | c] per channel
__device__ float g_wt0[96*64];                 // W0^T padded to K=96
__device__ float g_wt1[64*128];                // W1^T
__device__ float g_wt2[128*256];               // W2^T

__device__ __forceinline__ float lrelu(float v){ return v >= 0.f ? v : ALPHA_*v; }

typedef unsigned long long u64;
__device__ __forceinline__ void ffma2(u64 &d, u64 a, u64 b){
    asm("fma.rn.f32x2 %0, %1, %2, %0;" : "+l"(d) : "l"(a), "l"(b));
}
__device__ __forceinline__ u64 fma2n(u64 a, u64 b, u64 c){
    u64 d; asm("fma.rn.f32x2 %0, %1, %2, %3;" : "=l"(d) : "l"(a), "l"(b), "l"(c)); return d;
}
__device__ __forceinline__ u64 add2(u64 a, u64 b){
    u64 d; asm("add.rn.f32x2 %0, %1, %2;" : "=l"(d) : "l"(a), "l"(b)); return d;
}
__device__ __forceinline__ u64 mul2(u64 a, u64 b){
    u64 d; asm("mul.rn.f32x2 %0, %1, %2;" : "=l"(d) : "l"(a), "l"(b)); return d;
}
__device__ __forceinline__ u64 pack2(float lo, float hi){
    u64 d; asm("mov.b64 %0, {%1,%2};" : "=l"(d) : "f"(lo), "f"(hi)); return d;
}
__device__ __forceinline__ u64 splat2(float v){
    u64 d; asm("mov.b64 %0, {%1,%1};" : "=l"(d) : "f"(v)); return d;
}
__device__ __forceinline__ float2 u2f2(u64 u){
    float2 f; asm("mov.b64 {%0,%1}, %2;" : "=f"(f.x), "=f"(f.y) : "l"(u)); return f;
}

// argmax step across lanes: distances >= 0 so float bits are uint-ordered;
// lane order is index-ascending, so lowest set ballot lane = first occurrence.
__device__ __forceinline__ void warp_argmax(float &best, int &bi){
    unsigned bb = __float_as_uint(best);
    unsigned mx = __reduce_max_sync(0xffffffffu, bb);
    unsigned who = __ballot_sync(0xffffffffu, bb == mx);
    int src = __ffs(who) - 1;
    bi = __shfl_sync(0xffffffffu, bi, src);
    best = __uint_as_float(mx);
}

// ---------------- FPS: one block per batch, 1024 threads, 8 pts/thread (f32x2) ----------------
__global__ void __launch_bounds__(1024) fps_kernel(const float* __restrict__ xyz,
                                                   float* __restrict__ newxyz){
    int b = blockIdx.x, t = threadIdx.x;
    const float* px = xyz + (size_t)b*N_*3;
    u64 X2[4], Y2[4], Z2[4];
    float D[8];
#pragma unroll
    for (int i=0;i<4;i++){
        int p0 = t*8 + 2*i, p1 = p0 + 1;
        X2[i] = pack2(px[p0*3+0], px[p1*3+0]);
        Y2[i] = pack2(px[p0*3+1], px[p1*3+1]);
        Z2[i] = pack2(px[p0*3+2], px[p1*3+2]);
        D[2*i] = 1e10f; D[2*i+1] = 1e10f;
    }
    __shared__ float s_last[3];
    __shared__ float s_val[32];
    __shared__ int   s_idx[32];
    if (t==0){
        s_last[0]=px[0]; s_last[1]=px[1]; s_last[2]=px[2];
        newxyz[0 + (size_t)b*Q_*3]=px[0];
        newxyz[1 + (size_t)b*Q_*3]=px[1];
        newxyz[2 + (size_t)b*Q_*3]=px[2];
    }
    __syncthreads();
    for (int j=1;j<Q_;j++){
        u64 nlx = splat2(-s_last[0]);
        u64 nly = splat2(-s_last[1]);
        u64 nlz = splat2(-s_last[2]);
        float best=-1.f; int bi=0;
#pragma unroll
        for (int i=0;i<4;i++){
            u64 dx = add2(X2[i], nlx);          // RN(x - lx) per lane
            u64 dy = add2(Y2[i], nly);
            u64 dz = add2(Z2[i], nlz);
            u64 tt = mul2(dx, dx);
            tt = fma2n(dy, dy, tt);
            tt = fma2n(dz, dz, tt);
            float2 d = u2f2(tt);
            float n0 = fminf(D[2*i],   d.x); D[2*i]   = n0;
            float n1 = fminf(D[2*i+1], d.y); D[2*i+1] = n1;
            if (n0 > best){ best=n0; bi=t*8+2*i; }      // strict > keeps lowest index
            if (n1 > best){ best=n1; bi=t*8+2*i+1; }
        }
        warp_argmax(best, bi);
        if ((t&31)==0){ s_val[t>>5]=best; s_idx[t>>5]=bi; }
        __syncthreads();
        if (t < 32){
            best = s_val[t]; bi = s_idx[t];
            warp_argmax(best, bi);
            if (t==0){
                const float* pp = px + (size_t)bi*3;   // L1-hot (96KB slice)
                float ax=pp[0], ay=pp[1], az=pp[2];
                s_last[0]=ax; s_last[1]=ay; s_last[2]=az;
                float* o = newxyz + (size_t)(b*Q_+j)*3;
                o[0]=ax; o[1]=ay; o[2]=az;
            }
        }
        __syncthreads();
    }
}

// ---------------- Ball query: one warp per (b,q) ----------------
__global__ void __launch_bounds__(256) ballquery_kernel(const float* __restrict__ xyz,
                                                        const float* __restrict__ newxyz,
                                                        int* __restrict__ nidx){
    int w = (blockIdx.x*256 + threadIdx.x) >> 5;   // 0..8191
    int lane = threadIdx.x & 31;
    int b = w >> 10;
    const float* px = xyz + (size_t)b*N_*3;
    const float* pq = newxyz + (size_t)w*3;
    float qx=pq[0], qy=pq[1], qz=pq[2];
    float qsq = __fadd_rn(__fadd_rn(__fmul_rn(qx,qx), __fmul_rn(qy,qy)), __fmul_rn(qz,qz));
    int* out = nidx + (size_t)w*S_;
    int cnt = 0, first = 0;
    for (int base=0; base<N_ && cnt<S_; base+=32){
        int p = base + lane;
        float x=px[p*3+0], y=px[p*3+1], z=px[p*3+2];
        float xsq = __fadd_rn(__fadd_rn(__fmul_rn(x,x), __fmul_rn(y,y)), __fmul_rn(z,z));
        float dot = __fmaf_rn(qz, z, __fmaf_rn(qy, y, __fmul_rn(qx, x)));
        float d2  = __fadd_rn(__fadd_rn(qsq, xsq), __fmul_rn(-2.0f, dot));
        bool in = d2 < R2_;
        unsigned bal = __ballot_sync(0xffffffffu, in);
        if (bal){
            if (cnt == 0) first = base + __ffs(bal) - 1;
            int r = __popc(bal & ((1u << lane) - 1u));
            if (in && (cnt + r < S_)) out[cnt + r] = p;
            cnt += __popc(bal);
        }
    }
    if (cnt < S_){
        int pad = (cnt > 0) ? first : 0;
        if (lane >= cnt) out[lane] = pad;
    }
}

// ---------------- features [B][64][N] -> ft [B][N][64] ----------------
__global__ void __launch_bounds__(256) transpose_feat(const float* __restrict__ f,
                                                      float* __restrict__ ft){
    __shared__ float st[64][33];
    int b = blockIdx.y;
    int n0 = blockIdx.x*32;
    int tid = threadIdx.x;
    int nn = tid & 31, c0 = tid >> 5;
#pragma unroll
    for (int c = c0; c < 64; c += 8)
        st[c][nn] = f[((size_t)b*64 + c)*N_ + n0 + nn];
    __syncthreads();
#pragma unroll
    for (int e = tid; e < 2048; e += 256){
        int nl = e >> 6, c = e & 63;
        ft[((size_t)b*N_ + n0 + nl)*64 + c] = st[c][nl];
    }
}

// ---------------- build x0 [67][M]: rel xyz + gathered features ----------------
__global__ void __launch_bounds__(256) build_x0(const float* __restrict__ xyz,
                                                const float* __restrict__ nxyz,
                                                const float* __restrict__ ft,
                                                const int* __restrict__ nidx,
                                                float* __restrict__ x0){
    int m = blockIdx.x*256 + threadIdx.x;
    int b = m >> 15;
    int q = (m >> 5) & (Q_-1);
    int p = nidx[m];
    const float* pc = xyz + ((size_t)b*N_ + p)*3;
    const float* qc = nxyz + ((size_t)(b*Q_ + q))*3;
    x0[(size_t)0*M_ + m] = pc[0]-qc[0];
    x0[(size_t)1*M_ + m] = pc[1]-qc[1];
    x0[(size_t)2*M_ + m] = pc[2]-qc[2];
    const float4* fr = (const float4*)(ft + ((size_t)b*N_ + p)*64);
#pragma unroll
    for (int c4=0;c4<16;c4++){
        float4 v = fr[c4];
        x0[(size_t)(3+4*c4+0)*M_ + m] = v.x;
        x0[(size_t)(3+4*c4+1)*M_ + m] = v.y;
        x0[(size_t)(3+4*c4+2)*M_ + m] = v.z;
        x0[(size_t)(3+4*c4+3)*M_ + m] = v.w;
    }
}

__global__ void zero_stats(){
    int t = threadIdx.x;
    if (t < 128) g_st0[t]=0.f;
    if (t < 256) g_st1[t]=0.f;
    g_st2[t]=0.f;   // t < 512
}

// ---------------- W[c][k] -> WT[k][c], zero-padded in k ----------------
__global__ void transpose_w(const float* __restrict__ W, float* __restrict__ WT,
                            int CIN, int COUT, int KPAD){
    int idx = blockIdx.x*256 + threadIdx.x;
    if (idx >= KPAD*COUT) return;
    int k = idx / COUT, c = idx - k*COUT;
    WT[idx] = (k < CIN) ? W[c*CIN + k] : 0.f;
}

// ---------------- GEMM: Y[COUT][M] = W X (+bias), f32x2, 8m x CPT-cout per thread ----
// W stored SPLATTED (w,w) in smem: ty-uniform broadcast LDS, no per-kk register
// splat MOVs -> inner loop is pure ffma2-bound. Same per-element accumulation
// order as R5 -> bit-identical outputs.
// TRANS: apply leaky(a*v+c) while loading X. DOMAX: shuffle max over S -> gmax.
template<int CIN, int KPAD, int COUT, int CT, bool TRANS, bool DOMAX>
__global__ void __launch_bounds__(256,2) gemm_kernel(
    const float* __restrict__ WT, const float* __restrict__ bias,
    const float* __restrict__ Xin, const float* __restrict__ ac,
    float* __restrict__ Yout, float* __restrict__ gstats, float* __restrict__ gmax)
{
    constexpr int KC=32, MT=128;
    constexpr int CPT = CT/16;                  // couts per thread (4 or 8)
    __shared__ __align__(16) float2 sW[KC*CT];  // splatted (w,w)
    __shared__ __align__(16) float  sX[KC*MT];
    int tid = threadIdx.x;
    int tx = tid & 15, ty = tid >> 4;
    int mbase = blockIdx.x * MT;
    int cbase = blockIdx.y * CT;

    u64 acc[CPT][4] = {};
    constexpr int NCH = KPAD/KC;
#pragma unroll 1
    for (int ch=0; ch<NCH; ++ch){
        int k0 = ch*KC;
        __syncthreads();
#pragma unroll
        for (int e = tid; e < KC*CT/4; e += 256){
            int kk = e / (CT/4), c4 = e - kk*(CT/4);
            float4 w4 = *(const float4*)&WT[(size_t)(k0+kk)*COUT + cbase + c4*4];
            sW[kk*CT + c4*4 + 0] = make_float2(w4.x, w4.x);
            sW[kk*CT + c4*4 + 1] = make_float2(w4.y, w4.y);
            sW[kk*CT + c4*4 + 2] = make_float2(w4.z, w4.z);
            sW[kk*CT + c4*4 + 3] = make_float2(w4.w, w4.w);
        }
#pragma unroll
        for (int e = tid; e < KC*MT/4; e += 256){
            int kk = e >> 5, m4 = e & 31;
            int k = k0 + kk;
            float4 v = make_float4(0.f,0.f,0.f,0.f);
            if (k < CIN){
                v = *(const float4*)(Xin + (size_t)k*M_ + mbase + m4*4);
                if constexpr (TRANS){
                    float a = ac[k], c2 = ac[CIN + k];
                    v.x = lrelu(a*v.x + c2);
                    v.y = lrelu(a*v.y + c2);
                    v.z = lrelu(a*v.z + c2);
                    v.w = lrelu(a*v.w + c2);
                }
            }
            *(float4*)&sX[kk*MT + m4*4] = v;
        }
        __syncthreads();
#pragma unroll
        for (int kk=0; kk<KC; ++kk){
            const u64* wp = (const u64*)&sW[kk*CT + ty*CPT];
            u64 wsp[CPT];
#pragma unroll
            for (int i2=0; i2<CPT/2; i2++){
                ulonglong2 wv = *(const ulonglong2*)&wp[i2*2];   // broadcast LDS.128
                wsp[i2*2+0] = wv.x; wsp[i2*2+1] = wv.y;
            }
            ulonglong2 xa = *(const ulonglong2*)&sX[kk*MT + tx*8];
            ulonglong2 xb = *(const ulonglong2*)&sX[kk*MT + tx*8 + 4];
            u64 xv[4] = {xa.x, xa.y, xb.x, xb.y};
#pragma unroll
            for (int i=0;i<CPT;i++)
#pragma unroll
                for (int jj=0;jj<4;jj++)
                    ffma2(acc[i][jj], wsp[i], xv[jj]);
        }
    }

    // -------- epilogue: one cout row at a time --------
#pragma unroll
    for (int i=0;i<CPT;i++){
        int c = cbase + ty*CPT + i;
        float bi = bias[c];
        float vals[8];
        float s1 = 0.f, s2 = 0.f;
#pragma unroll
        for (int jj=0;jj<4;jj++){
            float2 f = u2f2(acc[i][jj]);
            f.x += bi; f.y += bi;
            vals[2*jj] = f.x; vals[2*jj+1] = f.y;
            s1 += f.x + f.y;
            s2 += f.x*f.x + f.y*f.y;
        }
#pragma unroll
        for (int o=1;o<16;o<<=1){
            s1 += __shfl_xor_sync(0xffffffffu, s1, o);
            s2 += __shfl_xor_sync(0xffffffffu, s2, o);
        }
        if (tx==0){
            atomicAdd(&gstats[c], s1);
            atomicAdd(&gstats[COUT + c], s2);
        }
        if constexpr (DOMAX){
            float v = vals[0];
#pragma unroll
            for (int s=1;s<8;s++) v = fmaxf(v, vals[s]);
            v = fmaxf(v, __shfl_xor_sync(0xffffffffu, v, 1));
            v = fmaxf(v, __shfl_xor_sync(0xffffffffu, v, 2));
            if ((tx&3)==0)
                gmax[(size_t)c*(B_*Q_) + (mbase>>5) + (tx>>2)] = v;
        } else {
            float* yp = Yout + (size_t)c*M_ + mbase + tx*8;
            *(float4*)yp     = make_float4(vals[0],vals[1],vals[2],vals[3]);
            *(float4*)(yp+4) = make_float4(vals[4],vals[5],vals[6],vals[7]);
        }
    }
}

template<int COUT>
__global__ void compute_ac(const float* __restrict__ st, const float* __restrict__ g,
                           const float* __restrict__ beta, float* __restrict__ ac){
    int c = threadIdx.x;
    if (c >= COUT) return;
    float inv  = 1.f/(float)M_;
    float mean = st[c]*inv;
    float var  = st[COUT+c]*inv - mean*mean;
    float a    = g[c]*rsqrtf(var + EPS_);
    ac[c]      = a;
    ac[COUT+c] = beta[c] - a*mean;
}

// out[b][c][q] = leaky(a2[c]*max + c2[c])   (BN+LeakyReLU commute with max since a2>0)
__global__ void __launch_bounds__(256) final_kernel(const float* __restrict__ gmax,
                                                    const float* __restrict__ ac,
                                                    float* __restrict__ out){
    int i = blockIdx.x*256 + threadIdx.x;
    int q = i & (Q_-1);
    int c = (i >> 10) & 255;
    int b = i >> 18;
    float a = ac[c], c2 = ac[256+c];
    out[i] = lrelu(a*gmax[(size_t)c*(B_*Q_) + b*Q_ + q] + c2);
}

extern "C" void kernel_launch(void* const* d_in, const int* in_sizes, int n_in,
                              void* d_out, int out_size) {
    const float* xyz  = (const float*)d_in[0];
    const float* feat = (const float*)d_in[1];
    const float* W0 = (const float*)d_in[2];
    const float* b0 = (const float*)d_in[3];
    const float* gg0= (const float*)d_in[4];
    const float* be0= (const float*)d_in[5];
    const float* W1 = (const float*)d_in[6];
    const float* b1 = (const float*)d_in[7];
    const float* gg1= (const float*)d_in[8];
    const float* be1= (const float*)d_in[9];
    const float* W2 = (const float*)d_in[10];
    const float* b2 = (const float*)d_in[11];
    const float* gg2= (const float*)d_in[12];
    const float* be2= (const float*)d_in[13];

    float* out = (float*)d_out;
    float* newxyz  = out;                          // [B][Q][3]
    float* outfeat = out + (size_t)B_*Q_*3;        // [B][256][Q]

    float *x0p,*y0p,*y1p,*ftp,*gmaxp,*st0p,*st1p,*st2p,*ac0p,*ac1p,*ac2p;
    float *wt0p,*wt1p,*wt2p; int* idxp;
    cudaGetSymbolAddress((void**)&x0p,  g_x0);
    cudaGetSymbolAddress((void**)&y0p,  g_y0);
    cudaGetSymbolAddress((void**)&y1p,  g_y1);
    cudaGetSymbolAddress((void**)&ftp,  g_ft);
    cudaGetSymbolAddress((void**)&gmaxp,g_gmax);
    cudaGetSymbolAddress((void**)&idxp, g_nidx);
    cudaGetSymbolAddress((void**)&st0p, g_st0);
    cudaGetSymbolAddress((void**)&st1p, g_st1);
    cudaGetSymbolAddress((void**)&st2p, g_st2);
    cudaGetSymbolAddress((void**)&ac0p, g_ac0);
    cudaGetSymbolAddress((void**)&ac1p, g_ac1);
    cudaGetSymbolAddress((void**)&ac2p, g_ac2);
    cudaGetSymbolAddress((void**)&wt0p, g_wt0);
    cudaGetSymbolAddress((void**)&wt1p, g_wt1);
    cudaGetSymbolAddress((void**)&wt2p, g_wt2);

    fps_kernel<<<B_, 1024>>>(xyz, newxyz);
    ballquery_kernel<<<(B_*Q_)/8, 256>>>(xyz, newxyz, idxp);
    transpose_feat<<<dim3(N_/32, B_), 256>>>(feat, ftp);
    build_x0<<<M_/256, 256>>>(xyz, newxyz, ftp, idxp, x0p);
    zero_stats<<<1, 512>>>();
    transpose_w<<<(96*64+255)/256,   256>>>(W0, wt0p, 67, 64, 96);
    transpose_w<<<(64*128+255)/256,  256>>>(W1, wt1p, 64, 128, 64);
    transpose_w<<<(128*256+255)/256, 256>>>(W2, wt2p, 128, 256, 128);

    gemm_kernel<67,96,64,64,false,false><<<dim3(M_/128, 1), 256>>>(wt0p, b0, x0p, nullptr, y0p, st0p, nullptr);
    compute_ac<64><<<1, 64>>>(st0p, gg0, be0, ac0p);

    gemm_kernel<64,64,128,128,true,false><<<dim3(M_/128, 1), 256>>>(wt1p, b1, y0p, ac0p, y1p, st1p, nullptr);
    compute_ac<128><<<1, 128>>>(st1p, gg1, be1, ac1p);

    gemm_kernel<128,128,256,128,true,true><<<dim3(M_/128, 2), 256>>>(wt2p, b2, y1p, ac1p, nullptr, st2p, gmaxp);
    compute_ac<256><<<1, 256>>>(st2p, gg2, be2, ac2p);

    final_kernel<<<(B_*256*Q_)/256, 256>>>(gmaxp, ac2p, outfeat);
}

// round 8
// speedup vs baseline: 2.3440x; 1.2647x over previous
#include <cuda_runtime.h>
#include <cstdint>

#define B_ 8
#define N_ 8192
#define Q_ 1024
#define S_ 32
#define M_ (B_*Q_*S_)          // 262144
#define R2_ 0.04f
#define ALPHA_ 0.2f
#define EPS_ 1e-5f

// ---------------- scratch (device globals: no allocations allowed) ----------------
__device__ float g_x0[(size_t)67*M_];          // [67][M]  grouped input
__device__ float g_y0[(size_t)64*M_];          // layer0 raw output
__device__ float g_y1[(size_t)128*M_];         // layer1 raw output
__device__ float g_ft[(size_t)B_*N_*64];       // features transposed [B][N][64]
__device__ float g_gmax[(size_t)256*B_*Q_];    // layer2 max over S (pre-BN)
__device__ int   g_nidx[M_];                   // ball query indices
__device__ float g_st0[2*64], g_st1[2*128], g_st2[2*256];   // [sum | sumsq]
__device__ float g_ac0[2*64], g_ac1[2*128], g_ac2[2*256];   // [a | c] per channel
__device__ float g_wt0[96*64];                 // W0^T (tf32-quantized), K-padded
__device__ float g_wt1[64*128];                // W1^T
__device__ float g_wt2[128*256];               // W2^T

__device__ __forceinline__ float lrelu(float v){ return v >= 0.f ? v : ALPHA_*v; }

// tf32 quantization (cuBLAS-style round-to-nearest)
__device__ __forceinline__ float tf32r(float x){
    unsigned r; asm("cvt.rna.tf32.f32 %0, %1;" : "=r"(r) : "f"(x));
    return __uint_as_float(r);
}

typedef unsigned long long u64;
__device__ __forceinline__ u64 fma2n(u64 a, u64 b, u64 c){
    u64 d; asm("fma.rn.f32x2 %0, %1, %2, %3;" : "=l"(d) : "l"(a), "l"(b), "l"(c)); return d;
}
__device__ __forceinline__ u64 add2(u64 a, u64 b){
    u64 d; asm("add.rn.f32x2 %0, %1, %2;" : "=l"(d) : "l"(a), "l"(b)); return d;
}
__device__ __forceinline__ u64 mul2(u64 a, u64 b){
    u64 d; asm("mul.rn.f32x2 %0, %1, %2;" : "=l"(d) : "l"(a), "l"(b)); return d;
}
__device__ __forceinline__ u64 pack2(float lo, float hi){
    u64 d; asm("mov.b64 %0, {%1,%2};" : "=l"(d) : "f"(lo), "f"(hi)); return d;
}
__device__ __forceinline__ u64 splat2(float v){
    u64 d; asm("mov.b64 %0, {%1,%1};" : "=l"(d) : "f"(v)); return d;
}
__device__ __forceinline__ float2 u2f2(u64 u){
    float2 f; asm("mov.b64 {%0,%1}, %2;" : "=f"(f.x), "=f"(f.y) : "l"(u)); return f;
}

// legacy tensor-core mma (sm_80+, valid on compute_100 baseline target)
__device__ __forceinline__ void mma_tf32(float* d, uint32_t a0, uint32_t a1,
                                         uint32_t a2, uint32_t a3,
                                         uint32_t b0, uint32_t b1){
    asm volatile(
        "mma.sync.aligned.m16n8k8.row.col.f32.tf32.tf32.f32 "
        "{%0,%1,%2,%3}, {%4,%5,%6,%7}, {%8,%9}, {%0,%1,%2,%3};"
        : "+f"(d[0]), "+f"(d[1]), "+f"(d[2]), "+f"(d[3])
        : "r"(a0), "r"(a1), "r"(a2), "r"(a3), "r"(b0), "r"(b1));
}

// argmax step across lanes: distances >= 0 so float bits are uint-ordered;
// lowest set ballot lane = first occurrence (lane order is index-ascending).
__device__ __forceinline__ void warp_argmax(float &best, int &bi){
    unsigned bb = __float_as_uint(best);
    unsigned mx = __reduce_max_sync(0xffffffffu, bb);
    unsigned who = __ballot_sync(0xffffffffu, bb == mx);
    int src = __ffs(who) - 1;
    bi = __shfl_sync(0xffffffffu, bi, src);
    best = __uint_as_float(mx);
}

// ---------------- FPS: one block per batch, 1024 threads, single barrier/iter ----------------
__global__ void __launch_bounds__(1024) fps_kernel(const float* __restrict__ xyz,
                                                   float* __restrict__ newxyz){
    int b = blockIdx.x, t = threadIdx.x;
    int wid = t >> 5, lane = t & 31;
    const float* px = xyz + (size_t)b*N_*3;
    u64 X2[4], Y2[4], Z2[4];
    float D[8];
#pragma unroll
    for (int i=0;i<4;i++){
        int p0 = t*8 + 2*i, p1 = p0 + 1;
        X2[i] = pack2(px[p0*3+0], px[p1*3+0]);
        Y2[i] = pack2(px[p0*3+1], px[p1*3+1]);
        Z2[i] = pack2(px[p0*3+2], px[p1*3+2]);
        D[2*i] = 1e10f; D[2*i+1] = 1e10f;
    }
    __shared__ float s_val[2][32];
    __shared__ int   s_idx[2][32];
    float lx = px[0], ly = px[1], lz = px[2];
    if (t==0){
        newxyz[0 + (size_t)b*Q_*3]=lx;
        newxyz[1 + (size_t)b*Q_*3]=ly;
        newxyz[2 + (size_t)b*Q_*3]=lz;
    }
    for (int j=1;j<Q_;j++){
        int par = j & 1;
        u64 nlx = splat2(-lx), nly = splat2(-ly), nlz = splat2(-lz);
        float best=-1.f; int bi=0;
#pragma unroll
        for (int i=0;i<4;i++){
            u64 dx = add2(X2[i], nlx);
            u64 dy = add2(Y2[i], nly);
            u64 dz = add2(Z2[i], nlz);
            u64 tt = mul2(dx, dx);
            tt = fma2n(dy, dy, tt);
            tt = fma2n(dz, dz, tt);
            float2 d = u2f2(tt);
            float n0 = fminf(D[2*i],   d.x); D[2*i]   = n0;
            float n1 = fminf(D[2*i+1], d.y); D[2*i+1] = n1;
            if (n0 > best){ best=n0; bi=t*8+2*i; }
            if (n1 > best){ best=n1; bi=t*8+2*i+1; }
        }
        warp_argmax(best, bi);
        if (lane==0){ s_val[par][wid]=best; s_idx[par][wid]=bi; }
        __syncthreads();
        // every warp redundantly reduces the 32 per-warp winners (index-ordered)
        best = s_val[par][lane]; bi = s_idx[par][lane];
        warp_argmax(best, bi);
        const float* pp = px + (size_t)bi*3;   // broadcast load, L1-hot
        lx = pp[0]; ly = pp[1]; lz = pp[2];
        if (t==0){
            float* o = newxyz + (size_t)(b*Q_+j)*3;
            o[0]=lx; o[1]=ly; o[2]=lz;
        }
        // no 2nd barrier: next iter writes buffer par^1; warps can't lap (barrier above)
    }
}

// ---------------- Ball query: one warp per (b,q), XLA-matched rounding ----------------
__global__ void __launch_bounds__(256) ballquery_kernel(const float* __restrict__ xyz,
                                                        const float* __restrict__ newxyz,
                                                        int* __restrict__ nidx){
    int w = (blockIdx.x*256 + threadIdx.x) >> 5;
    int lane = threadIdx.x & 31;
    int b = w >> 10;
    const float* px = xyz + (size_t)b*N_*3;
    const float* pq = newxyz + (size_t)w*3;
    float qx=pq[0], qy=pq[1], qz=pq[2];
    float qsq = __fadd_rn(__fadd_rn(__fmul_rn(qx,qx), __fmul_rn(qy,qy)), __fmul_rn(qz,qz));
    int* out = nidx + (size_t)w*S_;
    int cnt = 0, first = 0;
    for (int base=0; base<N_ && cnt<S_; base+=32){
        int p = base + lane;
        float x=px[p*3+0], y=px[p*3+1], z=px[p*3+2];
        float xsq = __fadd_rn(__fadd_rn(__fmul_rn(x,x), __fmul_rn(y,y)), __fmul_rn(z,z));
        float dot = __fmaf_rn(qz, z, __fmaf_rn(qy, y, __fmul_rn(qx, x)));
        float d2  = __fadd_rn(__fadd_rn(qsq, xsq), __fmul_rn(-2.0f, dot));
        bool in = d2 < R2_;
        unsigned bal = __ballot_sync(0xffffffffu, in);
        if (bal){
            if (cnt == 0) first = base + __ffs(bal) - 1;
            int r = __popc(bal & ((1u << lane) - 1u));
            if (in && (cnt + r < S_)) out[cnt + r] = p;
            cnt += __popc(bal);
        }
    }
    if (cnt < S_){
        int pad = (cnt > 0) ? first : 0;
        if (lane >= cnt) out[lane] = pad;
    }
}

// ---------------- features [B][64][N] -> ft [B][N][64] ----------------
__global__ void __launch_bounds__(256) transpose_feat(const float* __restrict__ f,
                                                      float* __restrict__ ft){
    __shared__ float st[64][33];
    int b = blockIdx.y;
    int n0 = blockIdx.x*32;
    int tid = threadIdx.x;
    int nn = tid & 31, c0 = tid >> 5;
#pragma unroll
    for (int c = c0; c < 64; c += 8)
        st[c][nn] = f[((size_t)b*64 + c)*N_ + n0 + nn];
    __syncthreads();
#pragma unroll
    for (int e = tid; e < 2048; e += 256){
        int nl = e >> 6, c = e & 63;
        ft[((size_t)b*N_ + n0 + nl)*64 + c] = st[c][nl];
    }
}

// ---------------- build x0 [67][M]: rel xyz + gathered features ----------------
__global__ void __launch_bounds__(256) build_x0(const float* __restrict__ xyz,
                                                const float* __restrict__ nxyz,
                                                const float* __restrict__ ft,
                                                const int* __restrict__ nidx,
                                                float* __restrict__ x0){
    int m = blockIdx.x*256 + threadIdx.x;
    int b = m >> 15;
    int q = (m >> 5) & (Q_-1);
    int p = nidx[m];
    const float* pc = xyz + ((size_t)b*N_ + p)*3;
    const float* qc = nxyz + ((size_t)(b*Q_ + q))*3;
    x0[(size_t)0*M_ + m] = pc[0]-qc[0];
    x0[(size_t)1*M_ + m] = pc[1]-qc[1];
    x0[(size_t)2*M_ + m] = pc[2]-qc[2];
    const float4* fr = (const float4*)(ft + ((size_t)b*N_ + p)*64);
#pragma unroll
    for (int c4=0;c4<16;c4++){
        float4 v = fr[c4];
        x0[(size_t)(3+4*c4+0)*M_ + m] = v.x;
        x0[(size_t)(3+4*c4+1)*M_ + m] = v.y;
        x0[(size_t)(3+4*c4+2)*M_ + m] = v.z;
        x0[(size_t)(3+4*c4+3)*M_ + m] = v.w;
    }
}

__global__ void zero_stats(){
    int t = threadIdx.x;
    if (t < 128) g_st0[t]=0.f;
    if (t < 256) g_st1[t]=0.f;
    g_st2[t]=0.f;   // t < 512
}

// ---------------- W[c][k] -> WT[k][c], tf32-quantized, zero-padded in k ----------------
__global__ void transpose_w(const float* __restrict__ W, float* __restrict__ WT,
                            int CIN, int COUT, int KPAD){
    int idx = blockIdx.x*256 + threadIdx.x;
    if (idx >= KPAD*COUT) return;
    int k = idx / COUT, c = idx - k*COUT;
    WT[idx] = (k < CIN) ? tf32r(W[c*CIN + k]) : 0.f;
}

// ---------------- GEMM via legacy mma.sync m16n8k8 TF32 ----------------
// D[cout][m] = W x X. Block tile: CTILE=WY*16 couts x MT=WX*64 m. 8 warps.
// Warp tile: 16 cout x 64 m (8 n-tiles of m16n8k8). K chunked by 32.
// sW [CTILE][33], sX [MT][36] padded -> conflict-free fragment LDS.
// TRANS: fold prev BN+lrelu into X load. DOMAX: max over S=32 in epilogue.
template<int CIN, int KPAD, int WY, int WX, bool TRANS, bool DOMAX, int COUTTOT>
__global__ void __launch_bounds__(256,2) mma_gemm(
    const float* __restrict__ WT, const float* __restrict__ bias,
    const float* __restrict__ Xin, const float* __restrict__ ac,
    float* __restrict__ Yout, float* __restrict__ gstats, float* __restrict__ gmax)
{
    constexpr int CTILE = WY*16;
    constexpr int MT = WX*64;
    constexpr int NCH = KPAD/32;
    __shared__ float sW[CTILE*33];
    __shared__ float sX[MT*36];
    int tid = threadIdx.x;
    int wid = tid >> 5, lane = tid & 31;
    int wy = wid % WY, wx = wid / WY;
    int mbase = blockIdx.x * MT;
    int cbase = blockIdx.y * CTILE;
    int qr = lane >> 2, ql = lane & 3;      // quad-row / quad-lane

    float d[8][4];
#pragma unroll
    for (int i=0;i<8;i++){ d[i][0]=0.f; d[i][1]=0.f; d[i][2]=0.f; d[i][3]=0.f; }

#pragma unroll 1
    for (int ch = 0; ch < NCH; ++ch){
        int k0 = ch*32;
        __syncthreads();
        // fill sW: CTILE couts x 32 k  (WT already tf32-quantized + padded)
#pragma unroll
        for (int e = tid; e < CTILE*8; e += 256){
            int kk = e / (CTILE/4), c4 = e % (CTILE/4);
            float4 w = *(const float4*)&WT[(size_t)(k0+kk)*COUTTOT + cbase + c4*4];
            sW[(c4*4+0)*33 + kk] = w.x;
            sW[(c4*4+1)*33 + kk] = w.y;
            sW[(c4*4+2)*33 + kk] = w.z;
            sW[(c4*4+3)*33 + kk] = w.w;
        }
        // fill sX: MT m x 32 k, transposed to [m][k], BN-fold + tf32 quantize
#pragma unroll
        for (int e = tid; e < MT*8; e += 256){
            int kk = e / (MT/4), m4 = e % (MT/4);
            int k = k0 + kk;
            float4 v = make_float4(0.f,0.f,0.f,0.f);
            if (k < CIN){
                v = *(const float4*)(Xin + (size_t)k*M_ + mbase + m4*4);
                if constexpr (TRANS){
                    float a = ac[k], c2 = ac[CIN + k];
                    v.x = lrelu(a*v.x + c2);
                    v.y = lrelu(a*v.y + c2);
                    v.z = lrelu(a*v.z + c2);
                    v.w = lrelu(a*v.w + c2);
                }
                v.x = tf32r(v.x); v.y = tf32r(v.y);
                v.z = tf32r(v.z); v.w = tf32r(v.w);
            }
            sX[(m4*4+0)*36 + kk] = v.x;
            sX[(m4*4+1)*36 + kk] = v.y;
            sX[(m4*4+2)*36 + kk] = v.z;
            sX[(m4*4+3)*36 + kk] = v.w;
        }
        __syncthreads();
#pragma unroll
        for (int s = 0; s < 4; ++s){
            int kb = s*8 + ql;
            const float* w0 = &sW[(wy*16 + qr)*33];
            const float* w8 = &sW[(wy*16 + qr + 8)*33];
            uint32_t a0 = __float_as_uint(w0[kb]);
            uint32_t a1 = __float_as_uint(w8[kb]);
            uint32_t a2 = __float_as_uint(w0[kb+4]);
            uint32_t a3 = __float_as_uint(w8[kb+4]);
#pragma unroll
            for (int nt = 0; nt < 8; ++nt){
                const float* xb = &sX[(wx*64 + nt*8 + qr)*36 + s*8 + ql];
                uint32_t b0 = __float_as_uint(xb[0]);
                uint32_t b1 = __float_as_uint(xb[4]);
                mma_tf32(d[nt], a0, a1, a2, a3, b0, b1);
            }
        }
    }

    // -------- epilogue --------
    int cout0 = cbase + wy*16 + qr;
    int cout1 = cout0 + 8;
    float bi0 = bias[cout0], bi1 = bias[cout1];
    float s1a=0.f, s2a=0.f, s1b=0.f, s2b=0.f;
    float mxa[2] = {-1e30f,-1e30f}, mxb[2] = {-1e30f,-1e30f};
#pragma unroll
    for (int nt = 0; nt < 8; ++nt){
        float v0 = d[nt][0] + bi0, v1 = d[nt][1] + bi0;
        float v2 = d[nt][2] + bi1, v3 = d[nt][3] + bi1;
        s1a += v0 + v1;  s2a += v0*v0 + v1*v1;
        s1b += v2 + v3;  s2b += v2*v2 + v3*v3;
        if constexpr (DOMAX){
            int g = nt >> 2;
            mxa[g] = fmaxf(mxa[g], fmaxf(v0, v1));
            mxb[g] = fmaxf(mxb[g], fmaxf(v2, v3));
        } else {
            int m0 = mbase + wx*64 + nt*8 + ql*2;
            *(float2*)(Yout + (size_t)cout0*M_ + m0) = make_float2(v0, v1);
            *(float2*)(Yout + (size_t)cout1*M_ + m0) = make_float2(v2, v3);
        }
    }
    // reduce across the 4 quad-lanes (same qr)
#pragma unroll
    for (int o=1;o<4;o<<=1){
        s1a += __shfl_xor_sync(0xffffffffu, s1a, o);
        s2a += __shfl_xor_sync(0xffffffffu, s2a, o);
        s1b += __shfl_xor_sync(0xffffffffu, s1b, o);
        s2b += __shfl_xor_sync(0xffffffffu, s2b, o);
    }
    if constexpr (DOMAX){
#pragma unroll
        for (int g=0; g<2; ++g){
#pragma unroll
            for (int o=1;o<4;o<<=1){
                mxa[g] = fmaxf(mxa[g], __shfl_xor_sync(0xffffffffu, mxa[g], o));
                mxb[g] = fmaxf(mxb[g], __shfl_xor_sync(0xffffffffu, mxb[g], o));
            }
        }
        if (ql == 0){
            int sg = (mbase + wx*64) >> 5;
            gmax[(size_t)cout0*(B_*Q_) + sg + 0] = mxa[0];
            gmax[(size_t)cout0*(B_*Q_) + sg + 1] = mxa[1];
            gmax[(size_t)cout1*(B_*Q_) + sg + 0] = mxb[0];
            gmax[(size_t)cout1*(B_*Q_) + sg + 1] = mxb[1];
        }
    }
    if (ql == 0){
        atomicAdd(&gstats[cout0], s1a);
        atomicAdd(&gstats[COUTTOT + cout0], s2a);
        atomicAdd(&gstats[cout1], s1b);
        atomicAdd(&gstats[COUTTOT + cout1], s2b);
    }
}

template<int COUT>
__global__ void compute_ac(const float* __restrict__ st, const float* __restrict__ g,
                           const float* __restrict__ beta, float* __restrict__ ac){
    int c = threadIdx.x;
    if (c >= COUT) return;
    float inv  = 1.f/(float)M_;
    float mean = st[c]*inv;
    float var  = st[COUT+c]*inv - mean*mean;
    float a    = g[c]*rsqrtf(var + EPS_);
    ac[c]      = a;
    ac[COUT+c] = beta[c] - a*mean;
}

// out[b][c][q] = leaky(a2[c]*max + c2[c])   (BN+LeakyReLU commute with max since a2>0)
__global__ void __launch_bounds__(256) final_kernel(const float* __restrict__ gmax,
                                                    const float* __restrict__ ac,
                                                    float* __restrict__ out){
    int i = blockIdx.x*256 + threadIdx.x;
    int q = i & (Q_-1);
    int c = (i >> 10) & 255;
    int b = i >> 18;
    float a = ac[c], c2 = ac[256+c];
    out[i] = lrelu(a*gmax[(size_t)c*(B_*Q_) + b*Q_ + q] + c2);
}

extern "C" void kernel_launch(void* const* d_in, const int* in_sizes, int n_in,
                              void* d_out, int out_size) {
    const float* xyz  = (const float*)d_in[0];
    const float* feat = (const float*)d_in[1];
    const float* W0 = (const float*)d_in[2];
    const float* b0 = (const float*)d_in[3];
    const float* gg0= (const float*)d_in[4];
    const float* be0= (const float*)d_in[5];
    const float* W1 = (const float*)d_in[6];
    const float* b1 = (const float*)d_in[7];
    const float* gg1= (const float*)d_in[8];
    const float* be1= (const float*)d_in[9];
    const float* W2 = (const float*)d_in[10];
    const float* b2 = (const float*)d_in[11];
    const float* gg2= (const float*)d_in[12];
    const float* be2= (const float*)d_in[13];

    float* out = (float*)d_out;
    float* newxyz  = out;                          // [B][Q][3]
    float* outfeat = out + (size_t)B_*Q_*3;        // [B][256][Q]

    float *x0p,*y0p,*y1p,*ftp,*gmaxp,*st0p,*st1p,*st2p,*ac0p,*ac1p,*ac2p;
    float *wt0p,*wt1p,*wt2p; int* idxp;
    cudaGetSymbolAddress((void**)&x0p,  g_x0);
    cudaGetSymbolAddress((void**)&y0p,  g_y0);
    cudaGetSymbolAddress((void**)&y1p,  g_y1);
    cudaGetSymbolAddress((void**)&ftp,  g_ft);
    cudaGetSymbolAddress((void**)&gmaxp,g_gmax);
    cudaGetSymbolAddress((void**)&idxp, g_nidx);
    cudaGetSymbolAddress((void**)&st0p, g_st0);
    cudaGetSymbolAddress((void**)&st1p, g_st1);
    cudaGetSymbolAddress((void**)&st2p, g_st2);
    cudaGetSymbolAddress((void**)&ac0p, g_ac0);
    cudaGetSymbolAddress((void**)&ac1p, g_ac1);
    cudaGetSymbolAddress((void**)&ac2p, g_ac2);
    cudaGetSymbolAddress((void**)&wt0p, g_wt0);
    cudaGetSymbolAddress((void**)&wt1p, g_wt1);
    cudaGetSymbolAddress((void**)&wt2p, g_wt2);

    fps_kernel<<<B_, 1024>>>(xyz, newxyz);
    ballquery_kernel<<<(B_*Q_)/8, 256>>>(xyz, newxyz, idxp);
    transpose_feat<<<dim3(N_/32, B_), 256>>>(feat, ftp);
    build_x0<<<M_/256, 256>>>(xyz, newxyz, ftp, idxp, x0p);
    zero_stats<<<1, 512>>>();
    transpose_w<<<(96*64+255)/256,   256>>>(W0, wt0p, 67, 64, 96);
    transpose_w<<<(64*128+255)/256,  256>>>(W1, wt1p, 64, 128, 64);
    transpose_w<<<(128*256+255)/256, 256>>>(W2, wt2p, 128, 256, 128);

    // L0: 64 cout (WY=4) x 128 m (WX=2), X read once
    mma_gemm<67,96,4,2,false,false,64><<<dim3(M_/128, 1), 256>>>(
        wt0p, b0, x0p, nullptr, y0p, st0p, nullptr);
    compute_ac<64><<<1, 64>>>(st0p, gg0, be0, ac0p);

    // L1: 128 cout (WY=8) x 64 m, X read once
    mma_gemm<64,64,8,1,true,false,128><<<dim3(M_/64, 1), 256>>>(
        wt1p, b1, y0p, ac0p, y1p, st1p, nullptr);
    compute_ac<128><<<1, 128>>>(st1p, gg1, be1, ac1p);

    // L2: 2 tiles of 128 cout x 64 m, X read 2x, fused max-over-S
    mma_gemm<128,128,8,1,true,true,256><<<dim3(M_/64, 2), 256>>>(
        wt2p, b2, y1p, ac1p, nullptr, st2p, gmaxp);
    compute_ac<256><<<1, 256>>>(st2p, gg2, be2, ac2p);

    final_kernel<<<(B_*256*Q_)/256, 256>>>(gmaxp, ac2p, outfeat);
}

// round 11
// speedup vs baseline: 2.3637x; 1.0084x over previous
#include <cuda_runtime.h>
#include <cstdint>

#define B_ 8
#define N_ 8192
#define Q_ 1024
#define S_ 32
#define M_ (B_*Q_*S_)          // 262144
#define R2_ 0.04f
#define ALPHA_ 0.2f
#define EPS_ 1e-5f

// ---------------- scratch (device globals: no allocations allowed) ----------------
__device__ float g_x0[(size_t)67*M_];          // [67][M]  grouped input
__device__ float g_y0[(size_t)64*M_];          // layer0 raw output
__device__ float g_y1[(size_t)128*M_];         // layer1 raw output
__device__ float g_ft[(size_t)B_*N_*64];       // features transposed [B][N][64]
__device__ float g_gmax[(size_t)256*B_*Q_];    // layer2 max over S (pre-BN)
__device__ int   g_nidx[M_];                   // ball query indices
__device__ float g_st0[2*64], g_st1[2*128], g_st2[2*256];   // [sum | sumsq]
__device__ float g_ac0[2*64], g_ac1[2*128], g_ac2[2*256];   // [a | c] per channel
__device__ float g_wt0[96*64];                 // W0^T (tf32-quantized), K-padded
__device__ float g_wt1[64*128];                // W1^T
__device__ float g_wt2[128*256];               // W2^T

__device__ __forceinline__ float lrelu(float v){ return v >= 0.f ? v : ALPHA_*v; }

// tf32 quantization (cuBLAS-style round-to-nearest)
__device__ __forceinline__ float tf32r(float x){
    unsigned r; asm("cvt.rna.tf32.f32 %0, %1;" : "=r"(r) : "f"(x));
    return __uint_as_float(r);
}

typedef unsigned long long u64;
__device__ __forceinline__ u64 fma2n(u64 a, u64 b, u64 c){
    u64 d; asm("fma.rn.f32x2 %0, %1, %2, %3;" : "=l"(d) : "l"(a), "l"(b), "l"(c)); return d;
}
__device__ __forceinline__ u64 add2(u64 a, u64 b){
    u64 d; asm("add.rn.f32x2 %0, %1, %2;" : "=l"(d) : "l"(a), "l"(b)); return d;
}
__device__ __forceinline__ u64 mul2(u64 a, u64 b){
    u64 d; asm("mul.rn.f32x2 %0, %1, %2;" : "=l"(d) : "l"(a), "l"(b)); return d;
}
__device__ __forceinline__ u64 pack2(float lo, float hi){
    u64 d; asm("mov.b64 %0, {%1,%2};" : "=l"(d) : "f"(lo), "f"(hi)); return d;
}
__device__ __forceinline__ u64 splat2(float v){
    u64 d; asm("mov.b64 %0, {%1,%1};" : "=l"(d) : "f"(v)); return d;
}
__device__ __forceinline__ float2 u2f2(u64 u){
    float2 f; asm("mov.b64 {%0,%1}, %2;" : "=f"(f.x), "=f"(f.y) : "l"(u)); return f;
}

// legacy tensor-core mma (sm_80+, valid on compute_100 baseline target)
__device__ __forceinline__ void mma_tf32(float* d, uint32_t a0, uint32_t a1,
                                         uint32_t a2, uint32_t a3,
                                         uint32_t b0, uint32_t b1){
    asm volatile(
        "mma.sync.aligned.m16n8k8.row.col.f32.tf32.tf32.f32 "
        "{%0,%1,%2,%3}, {%4,%5,%6,%7}, {%8,%9}, {%0,%1,%2,%3};"
        : "+f"(d[0]), "+f"(d[1]), "+f"(d[2]), "+f"(d[3])
        : "r"(a0), "r"(a1), "r"(a2), "r"(a3), "r"(b0), "r"(b1));
}

// argmax step across 32 index-ordered candidates (values >= 0)
__device__ __forceinline__ void warp_argmax(float &best, int &bi){
    unsigned bb = __float_as_uint(best);
    unsigned mx = __reduce_max_sync(0xffffffffu, bb);
    unsigned who = __ballot_sync(0xffffffffu, bb == mx);
    int src = __ffs(who) - 1;
    bi = __shfl_sync(0xffffffffu, bi, src);
    best = __uint_as_float(mx);
}

// ---------------- FPS: one block per batch, 1024 threads, single barrier/iter ----------------
// Per-thread argmax bookkeeping removed: value-only min/max updates, index
// recovered by equality scan on the single winning lane (first-occurrence kept:
// descending-slot scan with overwrite -> lowest index wins ties).
__global__ void __launch_bounds__(1024) fps_kernel(const float* __restrict__ xyz,
                                                   float* __restrict__ newxyz){
    int b = blockIdx.x, t = threadIdx.x;
    int wid = t >> 5, lane = t & 31;
    const float* px = xyz + (size_t)b*N_*3;
    u64 X2[4], Y2[4], Z2[4];
    float D[8];
#pragma unroll
    for (int i=0;i<4;i++){
        int p0 = t*8 + 2*i, p1 = p0 + 1;
        X2[i] = pack2(px[p0*3+0], px[p1*3+0]);
        Y2[i] = pack2(px[p0*3+1], px[p1*3+1]);
        Z2[i] = pack2(px[p0*3+2], px[p1*3+2]);
        D[2*i] = 1e10f; D[2*i+1] = 1e10f;
    }
    __shared__ float s_val[2][32];
    __shared__ int   s_idx[2][32];
    float lx = px[0], ly = px[1], lz = px[2];
    if (t==0){
        newxyz[0 + (size_t)b*Q_*3]=lx;
        newxyz[1 + (size_t)b*Q_*3]=ly;
        newxyz[2 + (size_t)b*Q_*3]=lz;
    }
    for (int j=1;j<Q_;j++){
        int par = j & 1;
        u64 nlx = splat2(-lx), nly = splat2(-ly), nlz = splat2(-lz);
#pragma unroll
        for (int i=0;i<4;i++){
            u64 dx = add2(X2[i], nlx);
            u64 dy = add2(Y2[i], nly);
            u64 dz = add2(Z2[i], nlz);
            u64 tt = mul2(dx, dx);
            tt = fma2n(dy, dy, tt);
            tt = fma2n(dz, dz, tt);
            float2 d = u2f2(tt);
            D[2*i]   = fminf(D[2*i],   d.x);
            D[2*i+1] = fminf(D[2*i+1], d.y);
        }
        float vbest = fmaxf(fmaxf(fmaxf(D[0],D[1]), fmaxf(D[2],D[3])),
                            fmaxf(fmaxf(D[4],D[5]), fmaxf(D[6],D[7])));
        unsigned mx = __reduce_max_sync(0xffffffffu, __float_as_uint(vbest));
        unsigned who = __ballot_sync(0xffffffffu, __float_as_uint(vbest) == mx);
        int src = __ffs(who) - 1;
        int bi = 0;
        if (lane == src){                        // winning lane recovers index
#pragma unroll
            for (int i=7;i>=0;i--)
                if (__float_as_uint(D[i]) == mx) bi = t*8 + i;
        }
        bi = __shfl_sync(0xffffffffu, bi, src);
        if (lane==0){ s_val[par][wid]=__uint_as_float(mx); s_idx[par][wid]=bi; }
        __syncthreads();
        // every warp redundantly reduces the 32 per-warp winners (index-ordered)
        float best = s_val[par][lane]; bi = s_idx[par][lane];
        warp_argmax(best, bi);
        const float* pp = px + (size_t)bi*3;     // broadcast load, L1-hot
        lx = pp[0]; ly = pp[1]; lz = pp[2];
        if (t==0){
            float* o = newxyz + (size_t)(b*Q_+j)*3;
            o[0]=lx; o[1]=ly; o[2]=lz;
        }
    }
}

// ---------------- Ball query: one warp per (b,q), XLA-matched rounding ----------------
__global__ void __launch_bounds__(256) ballquery_kernel(const float* __restrict__ xyz,
                                                        const float* __restrict__ newxyz,
                                                        int* __restrict__ nidx){
    int w = (blockIdx.x*256 + threadIdx.x) >> 5;
    int lane = threadIdx.x & 31;
    int b = w >> 10;
    const float* px = xyz + (size_t)b*N_*3;
    const float* pq = newxyz + (size_t)w*3;
    float qx=pq[0], qy=pq[1], qz=pq[2];
    float qsq = __fadd_rn(__fadd_rn(__fmul_rn(qx,qx), __fmul_rn(qy,qy)), __fmul_rn(qz,qz));
    int* out = nidx + (size_t)w*S_;
    int cnt = 0, first = 0;
    for (int base=0; base<N_ && cnt<S_; base+=32){
        int p = base + lane;
        float x=px[p*3+0], y=px[p*3+1], z=px[p*3+2];
        float xsq = __fadd_rn(__fadd_rn(__fmul_rn(x,x), __fmul_rn(y,y)), __fmul_rn(z,z));
        float dot = __fmaf_rn(qz, z, __fmaf_rn(qy, y, __fmul_rn(qx, x)));
        float d2  = __fadd_rn(__fadd_rn(qsq, xsq), __fmul_rn(-2.0f, dot));
        bool in = d2 < R2_;
        unsigned bal = __ballot_sync(0xffffffffu, in);
        if (bal){
            if (cnt == 0) first = base + __ffs(bal) - 1;
            int r = __popc(bal & ((1u << lane) - 1u));
            if (in && (cnt + r < S_)) out[cnt + r] = p;
            cnt += __popc(bal);
        }
    }
    if (cnt < S_){
        int pad = (cnt > 0) ? first : 0;
        if (lane >= cnt) out[lane] = pad;
    }
}

// ---------------- features [B][64][N] -> ft [B][N][64] ----------------
__global__ void __launch_bounds__(256) transpose_feat(const float* __restrict__ f,
                                                      float* __restrict__ ft){
    __shared__ float st[64][33];
    int b = blockIdx.y;
    int n0 = blockIdx.x*32;
    int tid = threadIdx.x;
    int nn = tid & 31, c0 = tid >> 5;
#pragma unroll
    for (int c = c0; c < 64; c += 8)
        st[c][nn] = f[((size_t)b*64 + c)*N_ + n0 + nn];
    __syncthreads();
#pragma unroll
    for (int e = tid; e < 2048; e += 256){
        int nl = e >> 6, c = e & 63;
        ft[((size_t)b*N_ + n0 + nl)*64 + c] = st[c][nl];
    }
}

// ---------------- build x0 [67][M]: rel xyz + gathered features ----------------
__global__ void __launch_bounds__(256) build_x0(const float* __restrict__ xyz,
                                                const float* __restrict__ nxyz,
                                                const float* __restrict__ ft,
                                                const int* __restrict__ nidx,
                                                float* __restrict__ x0){
    int m = blockIdx.x*256 + threadIdx.x;
    int b = m >> 15;
    int q = (m >> 5) & (Q_-1);
    int p = nidx[m];
    const float* pc = xyz + ((size_t)b*N_ + p)*3;
    const float* qc = nxyz + ((size_t)(b*Q_ + q))*3;
    x0[(size_t)0*M_ + m] = pc[0]-qc[0];
    x0[(size_t)1*M_ + m] = pc[1]-qc[1];
    x0[(size_t)2*M_ + m] = pc[2]-qc[2];
    const float4* fr = (const float4*)(ft + ((size_t)b*N_ + p)*64);
#pragma unroll
    for (int c4=0;c4<16;c4++){
        float4 v = fr[c4];
        x0[(size_t)(3+4*c4+0)*M_ + m] = v.x;
        x0[(size_t)(3+4*c4+1)*M_ + m] = v.y;
        x0[(size_t)(3+4*c4+2)*M_ + m] = v.z;
        x0[(size_t)(3+4*c4+3)*M_ + m] = v.w;
    }
}

__global__ void zero_stats(){
    int t = threadIdx.x;
    if (t < 128) g_st0[t]=0.f;
    if (t < 256) g_st1[t]=0.f;
    g_st2[t]=0.f;   // t < 512
}

// ---------------- W[c][k] -> WT[k][c], tf32-quantized, zero-padded in k ----------------
__global__ void transpose_w(const float* __restrict__ W, float* __restrict__ WT,
                            int CIN, int COUT, int KPAD){
    int idx = blockIdx.x*256 + threadIdx.x;
    if (idx >= KPAD*COUT) return;
    int k = idx / COUT, c = idx - k*COUT;
    WT[idx] = (k < CIN) ? tf32r(W[c*CIN + k]) : 0.f;
}

// ---------------- GEMM via legacy mma.sync m16n8k8 TF32 ----------------
// D[cout][m] = W x X. Block: CTILE=WY*16 couts x MT=WX*NT*8 m, 8 warps (WY*WX).
// Warp tile: 16 cout x NT*8 m. K chunked by 32.
// sW [CTILE][33], sX [MT][36] padded -> conflict-free fragment LDS.
template<int CIN, int KPAD, int WY, int WX, int NT, bool TRANS, bool DOMAX, int COUTTOT>
__global__ void __launch_bounds__(256,2) mma_gemm(
    const float* __restrict__ WT, const float* __restrict__ bias,
    const float* __restrict__ Xin, const float* __restrict__ ac,
    float* __restrict__ Yout, float* __restrict__ gstats, float* __restrict__ gmax)
{
    constexpr int CTILE = WY*16;
    constexpr int MT = WX*NT*8;
    constexpr int NCH = KPAD/32;
    __shared__ float sW[CTILE*33];
    __shared__ float sX[MT*36];
    int tid = threadIdx.x;
    int wid = tid >> 5, lane = tid & 31;
    int wy = wid % WY, wx = wid / WY;
    int mbase = blockIdx.x * MT;
    int cbase = blockIdx.y * CTILE;
    int qr = lane >> 2, ql = lane & 3;      // quad-row / quad-lane
    int mwarp = wx*NT*8;

    float d[NT][4];
#pragma unroll
    for (int i=0;i<NT;i++){ d[i][0]=0.f; d[i][1]=0.f; d[i][2]=0.f; d[i][3]=0.f; }

#pragma unroll 1
    for (int ch = 0; ch < NCH; ++ch){
        int k0 = ch*32;
        __syncthreads();
#pragma unroll
        for (int e = tid; e < CTILE*8; e += 256){
            int kk = e / (CTILE/4), c4 = e % (CTILE/4);
            float4 w = *(const float4*)&WT[(size_t)(k0+kk)*COUTTOT + cbase + c4*4];
            sW[(c4*4+0)*33 + kk] = w.x;
            sW[(c4*4+1)*33 + kk] = w.y;
            sW[(c4*4+2)*33 + kk] = w.z;
            sW[(c4*4+3)*33 + kk] = w.w;
        }
#pragma unroll
        for (int e = tid; e < MT*8; e += 256){
            int kk = e / (MT/4), m4 = e % (MT/4);
            int k = k0 + kk;
            float4 v = make_float4(0.f,0.f,0.f,0.f);
            if (k < CIN){
                v = *(const float4*)(Xin + (size_t)k*M_ + mbase + m4*4);
                if constexpr (TRANS){
                    float a = ac[k], c2 = ac[CIN + k];
                    v.x = lrelu(a*v.x + c2);
                    v.y = lrelu(a*v.y + c2);
                    v.z = lrelu(a*v.z + c2);
                    v.w = lrelu(a*v.w + c2);
                }
                v.x = tf32r(v.x); v.y = tf32r(v.y);
                v.z = tf32r(v.z); v.w = tf32r(v.w);
            }
            sX[(m4*4+0)*36 + kk] = v.x;
            sX[(m4*4+1)*36 + kk] = v.y;
            sX[(m4*4+2)*36 + kk] = v.z;
            sX[(m4*4+3)*36 + kk] = v.w;
        }
        __syncthreads();
#pragma unroll
        for (int s = 0; s < 4; ++s){
            int kb = s*8 + ql;
            const float* w0 = &sW[(wy*16 + qr)*33];
            const float* w8 = &sW[(wy*16 + qr + 8)*33];
            uint32_t a0 = __float_as_uint(w0[kb]);
            uint32_t a1 = __float_as_uint(w8[kb]);
            uint32_t a2 = __float_as_uint(w0[kb+4]);
            uint32_t a3 = __float_as_uint(w8[kb+4]);
#pragma unroll
            for (int nt = 0; nt < NT; ++nt){
                const float* xb = &sX[(mwarp + nt*8 + qr)*36 + s*8 + ql];
                uint32_t b0 = __float_as_uint(xb[0]);
                uint32_t b1 = __float_as_uint(xb[4]);
                mma_tf32(d[nt], a0, a1, a2, a3, b0, b1);
            }
        }
    }

    // -------- epilogue --------
    int cout0 = cbase + wy*16 + qr;
    int cout1 = cout0 + 8;
    float bi0 = bias[cout0], bi1 = bias[cout1];
    float s1a=0.f, s2a=0.f, s1b=0.f, s2b=0.f;
    float mxa[NT/4], mxb[NT/4];
#pragma unroll
    for (int g=0; g<NT/4; ++g){ mxa[g] = -1e30f; mxb[g] = -1e30f; }
#pragma unroll
    for (int nt = 0; nt < NT; ++nt){
        float v0 = d[nt][0] + bi0, v1 = d[nt][1] + bi0;
        float v2 = d[nt][2] + bi1, v3 = d[nt][3] + bi1;
        s1a += v0 + v1;  s2a += v0*v0 + v1*v1;
        s1b += v2 + v3;  s2b += v2*v2 + v3*v3;
        if constexpr (DOMAX){
            int g = nt >> 2;
            mxa[g] = fmaxf(mxa[g], fmaxf(v0, v1));
            mxb[g] = fmaxf(mxb[g], fmaxf(v2, v3));
        } else {
            int m0 = mbase + mwarp + nt*8 + ql*2;
            *(float2*)(Yout + (size_t)cout0*M_ + m0) = make_float2(v0, v1);
            *(float2*)(Yout + (size_t)cout1*M_ + m0) = make_float2(v2, v3);
        }
    }
#pragma unroll
    for (int o=1;o<4;o<<=1){
        s1a += __shfl_xor_sync(0xffffffffu, s1a, o);
        s2a += __shfl_xor_sync(0xffffffffu, s2a, o);
        s1b += __shfl_xor_sync(0xffffffffu, s1b, o);
        s2b += __shfl_xor_sync(0xffffffffu, s2b, o);
    }
    if constexpr (DOMAX){
#pragma unroll
        for (int g=0; g<NT/4; ++g){
#pragma unroll
            for (int o=1;o<4;o<<=1){
                mxa[g] = fmaxf(mxa[g], __shfl_xor_sync(0xffffffffu, mxa[g], o));
                mxb[g] = fmaxf(mxb[g], __shfl_xor_sync(0xffffffffu, mxb[g], o));
            }
        }
        if (ql == 0){
            int sg = (mbase + mwarp) >> 5;
#pragma unroll
            for (int g=0; g<NT/4; ++g){
                gmax[(size_t)cout0*(B_*Q_) + sg + g] = mxa[g];
                gmax[(size_t)cout1*(B_*Q_) + sg + g] = mxb[g];
            }
        }
    }
    if (ql == 0){
        atomicAdd(&gstats[cout0], s1a);
        atomicAdd(&gstats[COUTTOT + cout0], s2a);
        atomicAdd(&gstats[cout1], s1b);
        atomicAdd(&gstats[COUTTOT + cout1], s2b);
    }
}

template<int COUT>
__global__ void compute_ac(const float* __restrict__ st, const float* __restrict__ g,
                           const float* __restrict__ beta, float* __restrict__ ac){
    int c = threadIdx.x;
    if (c >= COUT) return;
    float inv  = 1.f/(float)M_;
    float mean = st[c]*inv;
    float var  = st[COUT+c]*inv - mean*mean;
    float a    = g[c]*rsqrtf(var + EPS_);
    ac[c]      = a;
    ac[COUT+c] = beta[c] - a*mean;
}

// out[b][c][q] = leaky(a2[c]*max + c2[c])   (BN+LeakyReLU commute with max since a2>0)
__global__ void __launch_bounds__(256) final_kernel(const float* __restrict__ gmax,
                                                    const float* __restrict__ ac,
                                                    float* __restrict__ out){
    int i = blockIdx.x*256 + threadIdx.x;
    int q = i & (Q_-1);
    int c = (i >> 10) & 255;
    int b = i >> 18;
    float a = ac[c], c2 = ac[256+c];
    out[i] = lrelu(a*gmax[(size_t)c*(B_*Q_) + b*Q_ + q] + c2);
}

extern "C" void kernel_launch(void* const* d_in, const int* in_sizes, int n_in,
                              void* d_out, int out_size) {
    const float* xyz  = (const float*)d_in[0];
    const float* feat = (const float*)d_in[1];
    const float* W0 = (const float*)d_in[2];
    const float* b0 = (const float*)d_in[3];
    const float* gg0= (const float*)d_in[4];
    const float* be0= (const float*)d_in[5];
    const float* W1 = (const float*)d_in[6];
    const float* b1 = (const float*)d_in[7];
    const float* gg1= (const float*)d_in[8];
    const float* be1= (const float*)d_in[9];
    const float* W2 = (const float*)d_in[10];
    const float* b2 = (const float*)d_in[11];
    const float* gg2= (const float*)d_in[12];
    const float* be2= (const float*)d_in[13];

    float* out = (float*)d_out;
    float* newxyz  = out;                          // [B][Q][3]
    float* outfeat = out + (size_t)B_*Q_*3;        // [B][256][Q]

    float *x0p,*y0p,*y1p,*ftp,*gmaxp,*st0p,*st1p,*st2p,*ac0p,*ac1p,*ac2p;
    float *wt0p,*wt1p,*wt2p; int* idxp;
    cudaGetSymbolAddress((void**)&x0p,  g_x0);
    cudaGetSymbolAddress((void**)&y0p,  g_y0);
    cudaGetSymbolAddress((void**)&y1p,  g_y1);
    cudaGetSymbolAddress((void**)&ftp,  g_ft);
    cudaGetSymbolAddress((void**)&gmaxp,g_gmax);
    cudaGetSymbolAddress((void**)&idxp, g_nidx);
    cudaGetSymbolAddress((void**)&st0p, g_st0);
    cudaGetSymbolAddress((void**)&st1p, g_st1);
    cudaGetSymbolAddress((void**)&st2p, g_st2);
    cudaGetSymbolAddress((void**)&ac0p, g_ac0);
    cudaGetSymbolAddress((void**)&ac1p, g_ac1);
    cudaGetSymbolAddress((void**)&ac2p, g_ac2);
    cudaGetSymbolAddress((void**)&wt0p, g_wt0);
    cudaGetSymbolAddress((void**)&wt1p, g_wt1);
    cudaGetSymbolAddress((void**)&wt2p, g_wt2);

    fps_kernel<<<B_, 1024>>>(xyz, newxyz);
    ballquery_kernel<<<(B_*Q_)/8, 256>>>(xyz, newxyz, idxp);
    transpose_feat<<<dim3(N_/32, B_), 256>>>(feat, ftp);
    build_x0<<<M_/256, 256>>>(xyz, newxyz, ftp, idxp, x0p);
    zero_stats<<<1, 512>>>();
    transpose_w<<<(96*64+255)/256,   256>>>(W0, wt0p, 67, 64, 96);
    transpose_w<<<(64*128+255)/256,  256>>>(W1, wt1p, 64, 128, 64);
    transpose_w<<<(128*256+255)/256, 256>>>(W2, wt2p, 128, 256, 128);

    // L0: 64 cout (WY=4, WX=2, NT=8) x 128 m, X read once
    mma_gemm<67,96,4,2,8,false,false,64><<<dim3(M_/128, 1), 256>>>(
        wt0p, b0, x0p, nullptr, y0p, st0p, nullptr);
    compute_ac<64><<<1, 64>>>(st0p, gg0, be0, ac0p);

    // L1: 128 cout (WY=8, WX=1, NT=16) x 128 m, X read once
    mma_gemm<64,64,8,1,16,true,false,128><<<dim3(M_/128, 1), 256>>>(
        wt1p, b1, y0p, ac0p, y1p, st1p, nullptr);
    compute_ac<128><<<1, 128>>>(st1p, gg1, be1, ac1p);

    // L2: 2 tiles of 128 cout x 128 m, fused max-over-S
    mma_gemm<128,128,8,1,16,true,true,256><<<dim3(M_/128, 2), 256>>>(
        wt2p, b2, y1p, ac1p, nullptr, st2p, gmaxp);
    compute_ac<256><<<1, 256>>>(st2p, gg2, be2, ac2p);

    final_kernel<<<(B_*256*Q_)/256, 256>>>(gmaxp, ac2p, outfeat);
}

// round 12
// speedup vs baseline: 2.3750x; 1.0048x over previous
#include <cuda_runtime.h>
#include <cstdint>

#define B_ 8
#define N_ 8192
#define Q_ 1024
#define S_ 32
#define M_ (B_*Q_*S_)          // 262144
#define R2_ 0.04f
#define ALPHA_ 0.2f
#define EPS_ 1e-5f

// ---------------- scratch (device globals: no allocations allowed) ----------------
__device__ float g_y0[(size_t)64*M_];          // layer0 raw output
__device__ float g_y1[(size_t)128*M_];         // layer1 raw output
__device__ float g_ft[(size_t)B_*N_*64];       // features transposed [B][N][64]
__device__ float g_gmax[(size_t)256*B_*Q_];    // layer2 max over S (pre-BN)
__device__ int   g_nidx[M_];                   // ball query indices
__device__ float g_st0[2*64], g_st1[2*128], g_st2[2*256];   // [sum | sumsq]
__device__ float g_ac0[2*64], g_ac1[2*128], g_ac2[2*256];   // [a | c] per channel
__device__ float g_wt0[96*64];                 // W0^T (tf32-quantized), K-padded
__device__ float g_wt1[64*128];                // W1^T
__device__ float g_wt2[128*256];               // W2^T

__device__ __forceinline__ float lrelu(float v){ return v >= 0.f ? v : ALPHA_*v; }

// tf32 quantization (cuBLAS-style round-to-nearest)
__device__ __forceinline__ float tf32r(float x){
    unsigned r; asm("cvt.rna.tf32.f32 %0, %1;" : "=r"(r) : "f"(x));
    return __uint_as_float(r);
}

typedef unsigned long long u64;
__device__ __forceinline__ u64 fma2n(u64 a, u64 b, u64 c){
    u64 d; asm("fma.rn.f32x2 %0, %1, %2, %3;" : "=l"(d) : "l"(a), "l"(b), "l"(c)); return d;
}
__device__ __forceinline__ u64 add2(u64 a, u64 b){
    u64 d; asm("add.rn.f32x2 %0, %1, %2;" : "=l"(d) : "l"(a), "l"(b)); return d;
}
__device__ __forceinline__ u64 mul2(u64 a, u64 b){
    u64 d; asm("mul.rn.f32x2 %0, %1, %2;" : "=l"(d) : "l"(a), "l"(b)); return d;
}
__device__ __forceinline__ u64 pack2(float lo, float hi){
    u64 d; asm("mov.b64 %0, {%1,%2};" : "=l"(d) : "f"(lo), "f"(hi)); return d;
}
__device__ __forceinline__ u64 splat2(float v){
    u64 d; asm("mov.b64 %0, {%1,%1};" : "=l"(d) : "f"(v)); return d;
}
__device__ __forceinline__ float2 u2f2(u64 u){
    float2 f; asm("mov.b64 {%0,%1}, %2;" : "=f"(f.x), "=f"(f.y) : "l"(u)); return f;
}

// legacy tensor-core mma (sm_80+, valid on compute_100 baseline target)
__device__ __forceinline__ void mma_tf32(float* d, uint32_t a0, uint32_t a1,
                                         uint32_t a2, uint32_t a3,
                                         uint32_t b0, uint32_t b1){
    asm volatile(
        "mma.sync.aligned.m16n8k8.row.col.f32.tf32.tf32.f32 "
        "{%0,%1,%2,%3}, {%4,%5,%6,%7}, {%8,%9}, {%0,%1,%2,%3};"
        : "+f"(d[0]), "+f"(d[1]), "+f"(d[2]), "+f"(d[3])
        : "r"(a0), "r"(a1), "r"(a2), "r"(a3), "r"(b0), "r"(b1));
}

// argmax step across 32 index-ordered candidates (values >= 0)
__device__ __forceinline__ void warp_argmax(float &best, int &bi){
    unsigned bb = __float_as_uint(best);
    unsigned mx = __reduce_max_sync(0xffffffffu, bb);
    unsigned who = __ballot_sync(0xffffffffu, bb == mx);
    int src = __ffs(who) - 1;
    bi = __shfl_sync(0xffffffffu, bi, src);
    best = __uint_as_float(mx);
}

// ---------------- FPS: one block per batch, 1024 threads, single barrier/iter ----------------
__global__ void __launch_bounds__(1024) fps_kernel(const float* __restrict__ xyz,
                                                   float* __restrict__ newxyz){
    int b = blockIdx.x, t = threadIdx.x;
    int wid = t >> 5, lane = t & 31;
    const float* px = xyz + (size_t)b*N_*3;
    u64 X2[4], Y2[4], Z2[4];
    float D[8];
#pragma unroll
    for (int i=0;i<4;i++){
        int p0 = t*8 + 2*i, p1 = p0 + 1;
        X2[i] = pack2(px[p0*3+0], px[p1*3+0]);
        Y2[i] = pack2(px[p0*3+1], px[p1*3+1]);
        Z2[i] = pack2(px[p0*3+2], px[p1*3+2]);
        D[2*i] = 1e10f; D[2*i+1] = 1e10f;
    }
    __shared__ float s_val[2][32];
    __shared__ int   s_idx[2][32];
    float lx = px[0], ly = px[1], lz = px[2];
    if (t==0){
        newxyz[0 + (size_t)b*Q_*3]=lx;
        newxyz[1 + (size_t)b*Q_*3]=ly;
        newxyz[2 + (size_t)b*Q_*3]=lz;
    }
    for (int j=1;j<Q_;j++){
        int par = j & 1;
        u64 nlx = splat2(-lx), nly = splat2(-ly), nlz = splat2(-lz);
#pragma unroll
        for (int i=0;i<4;i++){
            u64 dx = add2(X2[i], nlx);
            u64 dy = add2(Y2[i], nly);
            u64 dz = add2(Z2[i], nlz);
            u64 tt = mul2(dx, dx);
            tt = fma2n(dy, dy, tt);
            tt = fma2n(dz, dz, tt);
            float2 d = u2f2(tt);
            D[2*i]   = fminf(D[2*i],   d.x);
            D[2*i+1] = fminf(D[2*i+1], d.y);
        }
        float vbest = fmaxf(fmaxf(fmaxf(D[0],D[1]), fmaxf(D[2],D[3])),
                            fmaxf(fmaxf(D[4],D[5]), fmaxf(D[6],D[7])));
        unsigned mx = __reduce_max_sync(0xffffffffu, __float_as_uint(vbest));
        unsigned who = __ballot_sync(0xffffffffu, __float_as_uint(vbest) == mx);
        int src = __ffs(who) - 1;
        int bi = 0;
        if (lane == src){                        // winning lane recovers index
#pragma unroll
            for (int i=7;i>=0;i--)
                if (__float_as_uint(D[i]) == mx) bi = t*8 + i;
        }
        bi = __shfl_sync(0xffffffffu, bi, src);
        if (lane==0){ s_val[par][wid]=__uint_as_float(mx); s_idx[par][wid]=bi; }
        __syncthreads();
        float best = s_val[par][lane]; bi = s_idx[par][lane];
        warp_argmax(best, bi);
        const float* pp = px + (size_t)bi*3;     // broadcast load, L1-hot
        lx = pp[0]; ly = pp[1]; lz = pp[2];
        if (t==0){
            float* o = newxyz + (size_t)(b*Q_+j)*3;
            o[0]=lx; o[1]=ly; o[2]=lz;
        }
    }
}

// ---------------- Ball query: one warp per (b,q), XLA-matched rounding ----------------
__global__ void __launch_bounds__(256) ballquery_kernel(const float* __restrict__ xyz,
                                                        const float* __restrict__ newxyz,
                                                        int* __restrict__ nidx){
    int w = (blockIdx.x*256 + threadIdx.x) >> 5;
    int lane = threadIdx.x & 31;
    int b = w >> 10;
    const float* px = xyz + (size_t)b*N_*3;
    const float* pq = newxyz + (size_t)w*3;
    float qx=pq[0], qy=pq[1], qz=pq[2];
    float qsq = __fadd_rn(__fadd_rn(__fmul_rn(qx,qx), __fmul_rn(qy,qy)), __fmul_rn(qz,qz));
    int* out = nidx + (size_t)w*S_;
    int cnt = 0, first = 0;
    for (int base=0; base<N_ && cnt<S_; base+=32){
        int p = base + lane;
        float x=px[p*3+0], y=px[p*3+1], z=px[p*3+2];
        float xsq = __fadd_rn(__fadd_rn(__fmul_rn(x,x), __fmul_rn(y,y)), __fmul_rn(z,z));
        float dot = __fmaf_rn(qz, z, __fmaf_rn(qy, y, __fmul_rn(qx, x)));
        float d2  = __fadd_rn(__fadd_rn(qsq, xsq), __fmul_rn(-2.0f, dot));
        bool in = d2 < R2_;
        unsigned bal = __ballot_sync(0xffffffffu, in);
        if (bal){
            if (cnt == 0) first = base + __ffs(bal) - 1;
            int r = __popc(bal & ((1u << lane) - 1u));
            if (in && (cnt + r < S_)) out[cnt + r] = p;
            cnt += __popc(bal);
        }
    }
    if (cnt < S_){
        int pad = (cnt > 0) ? first : 0;
        if (lane >= cnt) out[lane] = pad;
    }
}

// ---------------- features [B][64][N] -> ft [B][N][64] ----------------
__global__ void __launch_bounds__(256) transpose_feat(const float* __restrict__ f,
                                                      float* __restrict__ ft){
    __shared__ float st[64][33];
    int b = blockIdx.y;
    int n0 = blockIdx.x*32;
    int tid = threadIdx.x;
    int nn = tid & 31, c0 = tid >> 5;
#pragma unroll
    for (int c = c0; c < 64; c += 8)
        st[c][nn] = f[((size_t)b*64 + c)*N_ + n0 + nn];
    __syncthreads();
#pragma unroll
    for (int e = tid; e < 2048; e += 256){
        int nl = e >> 6, c = e & 63;
        ft[((size_t)b*N_ + n0 + nl)*64 + c] = st[c][nl];
    }
}

__global__ void zero_stats(){
    int t = threadIdx.x;
    if (t < 128) g_st0[t]=0.f;
    if (t < 256) g_st1[t]=0.f;
    g_st2[t]=0.f;   // t < 512
}

// ---------------- W[c][k] -> WT[k][c], tf32-quantized, zero-padded in k ----------------
__global__ void transpose_w(const float* __restrict__ W, float* __restrict__ WT,
                            int CIN, int COUT, int KPAD){
    int idx = blockIdx.x*256 + threadIdx.x;
    if (idx >= KPAD*COUT) return;
    int k = idx / COUT, c = idx - k*COUT;
    WT[idx] = (k < CIN) ? tf32r(W[c*CIN + k]) : 0.f;
}

#define PW 37   // smem pitch: b/a-fragment LDS conflict-free (5*qr+ql distinct mod 32)

// ---------------- L0 GEMM with fused gather (build_x0 eliminated) ----------------
// y0[64][M] = W0 x X0 where X0[k][m] = (k<3 ? rel-xyz : ft[b][p][k-3]),
// gathered directly into sX per k-chunk. Values bit-identical to the old
// build_x0 + load path (same subtract, same tf32r).
__global__ void __launch_bounds__(256,2) mma_gemm_l0(
    const float* __restrict__ WT, const float* __restrict__ bias,
    const float* __restrict__ xyz, const float* __restrict__ nxyz,
    const float* __restrict__ ft, const int* __restrict__ nidx,
    float* __restrict__ Yout, float* __restrict__ gstats)
{
    constexpr int WY=4, WX=2, NT=8;
    constexpr int CTILE = WY*16;    // 64
    constexpr int MT = WX*NT*8;     // 128
    constexpr int NCH = 3;          // KPAD=96
    __shared__ float sW[CTILE*PW];
    __shared__ float sX[MT*PW];
    int tid = threadIdx.x;
    int wid = tid >> 5, lane = tid & 31;
    int wy = wid % WY, wx = wid / WY;
    int mbase = blockIdx.x * MT;
    int qr = lane >> 2, ql = lane & 3;
    int mwarp = wx*NT*8;

    // per-thread gather state: each thread owns one m-row, half of its k's
    int mloc = tid & 127;
    int half = tid >> 7;                 // 0: kk 0-15, 1: kk 16-31
    int m = mbase + mloc;
    int gb = m >> 15;
    int gq = (m >> 5) & (Q_-1);
    int p = nidx[m];
    const float* pc = xyz + ((size_t)gb*N_ + p)*3;
    const float* qc = nxyz + ((size_t)(gb*Q_ + gq))*3;
    float rel0 = pc[0]-qc[0], rel1 = pc[1]-qc[1], rel2 = pc[2]-qc[2];
    const float* fr = ft + ((size_t)gb*N_ + p)*64;

    float d[NT][4];
#pragma unroll
    for (int i=0;i<NT;i++){ d[i][0]=0.f; d[i][1]=0.f; d[i][2]=0.f; d[i][3]=0.f; }

#pragma unroll 1
    for (int ch = 0; ch < NCH; ++ch){
        int k0 = ch*32;
        __syncthreads();
        // sW fill: 64 couts x 32 k
#pragma unroll
        for (int e = tid; e < CTILE*8; e += 256){
            int kk = e / (CTILE/4), c4 = e % (CTILE/4);
            float4 w = *(const float4*)&WT[(size_t)(k0+kk)*64 + c4*4];
            sW[(c4*4+0)*PW + kk] = w.x;
            sW[(c4*4+1)*PW + kk] = w.y;
            sW[(c4*4+2)*PW + kk] = w.z;
            sW[(c4*4+3)*PW + kk] = w.w;
        }
        // sX fill: gather (bank: 5*mloc+kk -> conflict-free scalar STS)
#pragma unroll
        for (int kk2 = 0; kk2 < 16; ++kk2){
            int kk = half*16 + kk2;
            int k = k0 + kk;
            float v;
            if (k < 3)       v = (k==0) ? rel0 : (k==1 ? rel1 : rel2);
            else if (k < 67) v = fr[k-3];
            else             v = 0.f;
            sX[mloc*PW + kk] = tf32r(v);
        }
        __syncthreads();
#pragma unroll
        for (int s = 0; s < 4; ++s){
            int kb = s*8 + ql;
            const float* w0 = &sW[(wy*16 + qr)*PW];
            const float* w8 = &sW[(wy*16 + qr + 8)*PW];
            uint32_t a0 = __float_as_uint(w0[kb]);
            uint32_t a1 = __float_as_uint(w8[kb]);
            uint32_t a2 = __float_as_uint(w0[kb+4]);
            uint32_t a3 = __float_as_uint(w8[kb+4]);
#pragma unroll
            for (int nt = 0; nt < NT; ++nt){
                const float* xb = &sX[(mwarp + nt*8 + qr)*PW + s*8 + ql];
                uint32_t b0 = __float_as_uint(xb[0]);
                uint32_t b1 = __float_as_uint(xb[4]);
                mma_tf32(d[nt], a0, a1, a2, a3, b0, b1);
            }
        }
    }

    // -------- epilogue --------
    int cout0 = wy*16 + qr;
    int cout1 = cout0 + 8;
    float bi0 = bias[cout0], bi1 = bias[cout1];
    float s1a=0.f, s2a=0.f, s1b=0.f, s2b=0.f;
#pragma unroll
    for (int nt = 0; nt < NT; ++nt){
        float v0 = d[nt][0] + bi0, v1 = d[nt][1] + bi0;
        float v2 = d[nt][2] + bi1, v3 = d[nt][3] + bi1;
        s1a += v0 + v1;  s2a += v0*v0 + v1*v1;
        s1b += v2 + v3;  s2b += v2*v2 + v3*v3;
        int m0 = mbase + mwarp + nt*8 + ql*2;
        *(float2*)(Yout + (size_t)cout0*M_ + m0) = make_float2(v0, v1);
        *(float2*)(Yout + (size_t)cout1*M_ + m0) = make_float2(v2, v3);
    }
#pragma unroll
    for (int o=1;o<4;o<<=1){
        s1a += __shfl_xor_sync(0xffffffffu, s1a, o);
        s2a += __shfl_xor_sync(0xffffffffu, s2a, o);
        s1b += __shfl_xor_sync(0xffffffffu, s1b, o);
        s2b += __shfl_xor_sync(0xffffffffu, s2b, o);
    }
    if (ql == 0){
        atomicAdd(&gstats[cout0], s1a);
        atomicAdd(&gstats[64 + cout0], s2a);
        atomicAdd(&gstats[cout1], s1b);
        atomicAdd(&gstats[64 + cout1], s2b);
    }
}

// ---------------- Generic GEMM via mma.sync m16n8k8 TF32 (L1/L2, R8 shapes) ----------------
template<int CIN, int KPAD, int WY, int WX, int NT, bool TRANS, bool DOMAX, int COUTTOT>
__global__ void __launch_bounds__(256,2) mma_gemm(
    const float* __restrict__ WT, const float* __restrict__ bias,
    const float* __restrict__ Xin, const float* __restrict__ ac,
    float* __restrict__ Yout, float* __restrict__ gstats, float* __restrict__ gmax)
{
    constexpr int CTILE = WY*16;
    constexpr int MT = WX*NT*8;
    constexpr int NCH = KPAD/32;
    __shared__ float sW[CTILE*PW];
    __shared__ float sX[MT*PW];
    int tid = threadIdx.x;
    int wid = tid >> 5, lane = tid & 31;
    int wy = wid % WY, wx = wid / WY;
    int mbase = blockIdx.x * MT;
    int cbase = blockIdx.y * CTILE;
    int qr = lane >> 2, ql = lane & 3;
    int mwarp = wx*NT*8;

    float d[NT][4];
#pragma unroll
    for (int i=0;i<NT;i++){ d[i][0]=0.f; d[i][1]=0.f; d[i][2]=0.f; d[i][3]=0.f; }

#pragma unroll 1
    for (int ch = 0; ch < NCH; ++ch){
        int k0 = ch*32;
        __syncthreads();
#pragma unroll
        for (int e = tid; e < CTILE*8; e += 256){
            int kk = e / (CTILE/4), c4 = e % (CTILE/4);
            float4 w = *(const float4*)&WT[(size_t)(k0+kk)*COUTTOT + cbase + c4*4];
            sW[(c4*4+0)*PW + kk] = w.x;
            sW[(c4*4+1)*PW + kk] = w.y;
            sW[(c4*4+2)*PW + kk] = w.z;
            sW[(c4*4+3)*PW + kk] = w.w;
        }
#pragma unroll
        for (int e = tid; e < MT*8; e += 256){
            int kk = e / (MT/4), m4 = e % (MT/4);
            int k = k0 + kk;
            float4 v = make_float4(0.f,0.f,0.f,0.f);
            if (k < CIN){
                v = *(const float4*)(Xin + (size_t)k*M_ + mbase + m4*4);
                if constexpr (TRANS){
                    float a = ac[k], c2 = ac[CIN + k];
                    v.x = lrelu(a*v.x + c2);
                    v.y = lrelu(a*v.y + c2);
                    v.z = lrelu(a*v.z + c2);
                    v.w = lrelu(a*v.w + c2);
                }
                v.x = tf32r(v.x); v.y = tf32r(v.y);
                v.z = tf32r(v.z); v.w = tf32r(v.w);
            }
            sX[(m4*4+0)*PW + kk] = v.x;
            sX[(m4*4+1)*PW + kk] = v.y;
            sX[(m4*4+2)*PW + kk] = v.z;
            sX[(m4*4+3)*PW + kk] = v.w;
        }
        __syncthreads();
#pragma unroll
        for (int s = 0; s < 4; ++s){
            int kb = s*8 + ql;
            const float* w0 = &sW[(wy*16 + qr)*PW];
            const float* w8 = &sW[(wy*16 + qr + 8)*PW];
            uint32_t a0 = __float_as_uint(w0[kb]);
            uint32_t a1 = __float_as_uint(w8[kb]);
            uint32_t a2 = __float_as_uint(w0[kb+4]);
            uint32_t a3 = __float_as_uint(w8[kb+4]);
#pragma unroll
            for (int nt = 0; nt < NT; ++nt){
                const float* xb = &sX[(mwarp + nt*8 + qr)*PW + s*8 + ql];
                uint32_t b0 = __float_as_uint(xb[0]);
                uint32_t b1 = __float_as_uint(xb[4]);
                mma_tf32(d[nt], a0, a1, a2, a3, b0, b1);
            }
        }
    }

    // -------- epilogue --------
    int cout0 = cbase + wy*16 + qr;
    int cout1 = cout0 + 8;
    float bi0 = bias[cout0], bi1 = bias[cout1];
    float s1a=0.f, s2a=0.f, s1b=0.f, s2b=0.f;
    float mxa[NT/4], mxb[NT/4];
#pragma unroll
    for (int g=0; g<NT/4; ++g){ mxa[g] = -1e30f; mxb[g] = -1e30f; }
#pragma unroll
    for (int nt = 0; nt < NT; ++nt){
        float v0 = d[nt][0] + bi0, v1 = d[nt][1] + bi0;
        float v2 = d[nt][2] + bi1, v3 = d[nt][3] + bi1;
        s1a += v0 + v1;  s2a += v0*v0 + v1*v1;
        s1b += v2 + v3;  s2b += v2*v2 + v3*v3;
        if constexpr (DOMAX){
            int g = nt >> 2;
            mxa[g] = fmaxf(mxa[g], fmaxf(v0, v1));
            mxb[g] = fmaxf(mxb[g], fmaxf(v2, v3));
        } else {
            int m0 = mbase + mwarp + nt*8 + ql*2;
            *(float2*)(Yout + (size_t)cout0*M_ + m0) = make_float2(v0, v1);
            *(float2*)(Yout + (size_t)cout1*M_ + m0) = make_float2(v2, v3);
        }
    }
#pragma unroll
    for (int o=1;o<4;o<<=1){
        s1a += __shfl_xor_sync(0xffffffffu, s1a, o);
        s2a += __shfl_xor_sync(0xffffffffu, s2a, o);
        s1b += __shfl_xor_sync(0xffffffffu, s1b, o);
        s2b += __shfl_xor_sync(0xffffffffu, s2b, o);
    }
    if constexpr (DOMAX){
#pragma unroll
        for (int g=0; g<NT/4; ++g){
#pragma unroll
            for (int o=1;o<4;o<<=1){
                mxa[g] = fmaxf(mxa[g], __shfl_xor_sync(0xffffffffu, mxa[g], o));
                mxb[g] = fmaxf(mxb[g], __shfl_xor_sync(0xffffffffu, mxb[g], o));
            }
        }
        if (ql == 0){
            int sg = (mbase + mwarp) >> 5;
#pragma unroll
            for (int g=0; g<NT/4; ++g){
                gmax[(size_t)cout0*(B_*Q_) + sg + g] = mxa[g];
                gmax[(size_t)cout1*(B_*Q_) + sg + g] = mxb[g];
            }
        }
    }
    if (ql == 0){
        atomicAdd(&gstats[cout0], s1a);
        atomicAdd(&gstats[COUTTOT + cout0], s2a);
        atomicAdd(&gstats[cout1], s1b);
        atomicAdd(&gstats[COUTTOT + cout1], s2b);
    }
}

template<int COUT>
__global__ void compute_ac(const float* __restrict__ st, const float* __restrict__ g,
                           const float* __restrict__ beta, float* __restrict__ ac){
    int c = threadIdx.x;
    if (c >= COUT) return;
    float inv  = 1.f/(float)M_;
    float mean = st[c]*inv;
    float var  = st[COUT+c]*inv - mean*mean;
    float a    = g[c]*rsqrtf(var + EPS_);
    ac[c]      = a;
    ac[COUT+c] = beta[c] - a*mean;
}

// out[b][c][q] = leaky(a2[c]*max + c2[c])   (BN+LeakyReLU commute with max since a2>0)
__global__ void __launch_bounds__(256) final_kernel(const float* __restrict__ gmax,
                                                    const float* __restrict__ ac,
                                                    float* __restrict__ out){
    int i = blockIdx.x*256 + threadIdx.x;
    int q = i & (Q_-1);
    int c = (i >> 10) & 255;
    int b = i >> 18;
    float a = ac[c], c2 = ac[256+c];
    out[i] = lrelu(a*gmax[(size_t)c*(B_*Q_) + b*Q_ + q] + c2);
}

extern "C" void kernel_launch(void* const* d_in, const int* in_sizes, int n_in,
                              void* d_out, int out_size) {
    const float* xyz  = (const float*)d_in[0];
    const float* feat = (const float*)d_in[1];
    const float* W0 = (const float*)d_in[2];
    const float* b0 = (const float*)d_in[3];
    const float* gg0= (const float*)d_in[4];
    const float* be0= (const float*)d_in[5];
    const float* W1 = (const float*)d_in[6];
    const float* b1 = (const float*)d_in[7];
    const float* gg1= (const float*)d_in[8];
    const float* be1= (const float*)d_in[9];
    const float* W2 = (const float*)d_in[10];
    const float* b2 = (const float*)d_in[11];
    const float* gg2= (const float*)d_in[12];
    const float* be2= (const float*)d_in[13];

    float* out = (float*)d_out;
    float* newxyz  = out;                          // [B][Q][3]
    float* outfeat = out + (size_t)B_*Q_*3;        // [B][256][Q]

    float *y0p,*y1p,*ftp,*gmaxp,*st0p,*st1p,*st2p,*ac0p,*ac1p,*ac2p;
    float *wt0p,*wt1p,*wt2p; int* idxp;
    cudaGetSymbolAddress((void**)&y0p,  g_y0);
    cudaGetSymbolAddress((void**)&y1p,  g_y1);
    cudaGetSymbolAddress((void**)&ftp,  g_ft);
    cudaGetSymbolAddress((void**)&gmaxp,g_gmax);
    cudaGetSymbolAddress((void**)&idxp, g_nidx);
    cudaGetSymbolAddress((void**)&st0p, g_st0);
    cudaGetSymbolAddress((void**)&st1p, g_st1);
    cudaGetSymbolAddress((void**)&st2p, g_st2);
    cudaGetSymbolAddress((void**)&ac0p, g_ac0);
    cudaGetSymbolAddress((void**)&ac1p, g_ac1);
    cudaGetSymbolAddress((void**)&ac2p, g_ac2);
    cudaGetSymbolAddress((void**)&wt0p, g_wt0);
    cudaGetSymbolAddress((void**)&wt1p, g_wt1);
    cudaGetSymbolAddress((void**)&wt2p, g_wt2);

    fps_kernel<<<B_, 1024>>>(xyz, newxyz);
    ballquery_kernel<<<(B_*Q_)/8, 256>>>(xyz, newxyz, idxp);
    transpose_feat<<<dim3(N_/32, B_), 256>>>(feat, ftp);
    zero_stats<<<1, 512>>>();
    transpose_w<<<(96*64+255)/256,   256>>>(W0, wt0p, 67, 64, 96);
    transpose_w<<<(64*128+255)/256,  256>>>(W1, wt1p, 64, 128, 64);
    transpose_w<<<(128*256+255)/256, 256>>>(W2, wt2p, 128, 256, 128);

    // L0: fused gather, 64 cout x 128 m
    mma_gemm_l0<<<M_/128, 256>>>(wt0p, b0, xyz, newxyz, ftp, idxp, y0p, st0p);
    compute_ac<64><<<1, 64>>>(st0p, gg0, be0, ac0p);

    // L1: 128 cout x 64 m (R8 shape)
    mma_gemm<64,64,8,1,8,true,false,128><<<dim3(M_/64, 1), 256>>>(
        wt1p, b1, y0p, ac0p, y1p, st1p, nullptr);
    compute_ac<128><<<1, 128>>>(st1p, gg1, be1, ac1p);

    // L2: 2 tiles of 128 cout x 64 m, fused max-over-S (R8 shape)
    mma_gemm<128,128,8,1,8,true,true,256><<<dim3(M_/64, 2), 256>>>(
        wt2p, b2, y1p, ac1p, nullptr, st2p, gmaxp);
    compute_ac<256><<<1, 256>>>(st2p, gg2, be2, ac2p);

    final_kernel<<<(B_*256*Q_)/256, 256>>>(gmaxp, ac2p, outfeat);
}